// round 1
// baseline (speedup 1.0000x reference)
#include <cuda_runtime.h>
#include <cuda_bf16.h>
#include <math.h>

// Problem constants
#define T_TOK 2048
#define HID   2048
#define NH    16
#define DN    128
#define DR    64
#define DV    128
#define KVD   512
#define DQK   192          // DN + DR
#define QDIM  (NH*DQK)     // 3072
#define KVADIM (KVD + DR)  // 576
#define KVBDIM (NH*(DN+DV)) // 4096
#define ODIM  (NH*DV)      // 2048
#define ATT_SCALE 0.07216878364870323f  // 1/sqrt(192)

// ---------------- scratch (device globals; no allocation allowed) ------------
__device__ float g_q[(size_t)T_TOK * QDIM];      // q (nope+pe), pe roped in place
__device__ float g_kv[(size_t)T_TOK * KVADIM];   // hs @ w_kv_a
__device__ float g_kvc[(size_t)T_TOK * KVD];     // rmsnormed latent
__device__ float g_kpe[(size_t)T_TOK * DR];      // roped k_pe
__device__ float g_kvb[(size_t)T_TOK * KVBDIM];  // kv_c @ w_kv_b  (per head: 128 k_nope | 128 v)
__device__ float g_attn[(size_t)T_TOK * ODIM];   // attention output

// ---------------- fp32 SGEMM: C[M,N] = A[M,K] @ B[K,N], row-major ------------
// 128x128 tile, BK=8, 256 threads, 8x8 microtile. M must be multiple of 128,
// K multiple of 8, N multiple of 4 (partial N tiles guarded).
__global__ __launch_bounds__(256) void sgemm(const float* __restrict__ A,
                                             const float* __restrict__ B,
                                             float* __restrict__ C,
                                             int M, int N, int K) {
    __shared__ float As[8][128];
    __shared__ float Bs[8][128];
    int tid  = threadIdx.x;
    int crow = blockIdx.y * 128;
    int ccol = blockIdx.x * 128;
    int aRow = tid >> 1;
    int aCol = (tid & 1) << 2;
    int bRow = tid >> 5;
    int bCol = (tid & 31) << 2;
    int ty = tid >> 4;
    int tx = tid & 15;

    float acc[8][8];
#pragma unroll
    for (int i = 0; i < 8; i++)
#pragma unroll
        for (int j = 0; j < 8; j++) acc[i][j] = 0.f;

    for (int k0 = 0; k0 < K; k0 += 8) {
        float4 a4 = *(const float4*)(A + (size_t)(crow + aRow) * K + k0 + aCol);
        As[aCol + 0][aRow] = a4.x;
        As[aCol + 1][aRow] = a4.y;
        As[aCol + 2][aRow] = a4.z;
        As[aCol + 3][aRow] = a4.w;
        float4 b4 = make_float4(0.f, 0.f, 0.f, 0.f);
        if (ccol + bCol < N)
            b4 = *(const float4*)(B + (size_t)(k0 + bRow) * N + ccol + bCol);
        *(float4*)(&Bs[bRow][bCol]) = b4;
        __syncthreads();
#pragma unroll
        for (int k = 0; k < 8; k++) {
            float ar[8], br[8];
            *(float4*)(ar)     = *(float4*)(&As[k][ty * 8]);
            *(float4*)(ar + 4) = *(float4*)(&As[k][ty * 8 + 4]);
            *(float4*)(br)     = *(float4*)(&Bs[k][tx * 8]);
            *(float4*)(br + 4) = *(float4*)(&Bs[k][tx * 8 + 4]);
#pragma unroll
            for (int i = 0; i < 8; i++)
#pragma unroll
                for (int j = 0; j < 8; j++)
                    acc[i][j] += ar[i] * br[j];
        }
        __syncthreads();
    }
#pragma unroll
    for (int i = 0; i < 8; i++) {
        int r = crow + ty * 8 + i;
#pragma unroll
        for (int j = 0; j < 8; j += 4) {
            int c = ccol + tx * 8 + j;
            if (c < N)
                *(float4*)(C + (size_t)r * N + c) =
                    make_float4(acc[i][j], acc[i][j+1], acc[i][j+2], acc[i][j+3]);
        }
    }
}

// ---------------- RMSNorm (kv latent) + RoPE (q_pe inplace, k_pe) ------------
__global__ __launch_bounds__(256) void norm_rope(const int* __restrict__ positions,
                                                 const float* __restrict__ lnw) {
    int t   = blockIdx.x;
    int tid = threadIdx.x;
    const float* kvrow = g_kv + (size_t)t * KVADIM;

    // sum of squares over 512
    float ss = 0.f;
    for (int i = tid; i < KVD; i += 256) {
        float v = kvrow[i];
        ss += v * v;
    }
#pragma unroll
    for (int o = 16; o > 0; o >>= 1) ss += __shfl_xor_sync(0xFFFFFFFFu, ss, o);
    __shared__ float red[8];
    if ((tid & 31) == 0) red[tid >> 5] = ss;
    __syncthreads();
    float tot = 0.f;
#pragma unroll
    for (int w = 0; w < 8; w++) tot += red[w];
    float inv = rsqrtf(tot * (1.f / KVD) + 1e-6f);

    for (int i = tid; i < KVD; i += 256)
        g_kvc[(size_t)t * KVD + i] = kvrow[i] * inv * lnw[i];

    float pos = (float)positions[t];

    // k_pe: 32 pairs
    for (int i = tid; i < DR / 2; i += 256) {
        float invf = (float)exp(-((double)(2 * i) / (double)DR) * 9.210340371976184);
        float f = pos * invf;
        float c = cosf(f), s = sinf(f);
        float x1 = kvrow[KVD + 2 * i];
        float x2 = kvrow[KVD + 2 * i + 1];
        g_kpe[(size_t)t * DR + 2 * i]     = x1 * c - x2 * s;
        g_kpe[(size_t)t * DR + 2 * i + 1] = x2 * c + x1 * s;
    }

    // q_pe: NH * 32 pairs, in place in g_q
    for (int idx = tid; idx < NH * (DR / 2); idx += 256) {
        int h = idx / (DR / 2);
        int i = idx % (DR / 2);
        float invf = (float)exp(-((double)(2 * i) / (double)DR) * 9.210340371976184);
        float f = pos * invf;
        float c = cosf(f), s = sinf(f);
        float* qp = g_q + (size_t)t * QDIM + h * DQK + DN + 2 * i;
        float x1 = qp[0], x2 = qp[1];
        qp[0] = x1 * c - x2 * s;
        qp[1] = x2 * c + x1 * s;
    }
}

// ---------------- flash attention, fp32, BQ=BK=64 ----------------------------
#define BQ 64
#define BKT 64
#define QP 196   // padded pitch for 192-wide rows (bank-conflict avoidance)
#define VP 132
#define SP 66

__global__ __launch_bounds__(256) void attn_kernel() {
    extern __shared__ float sm[];
    float* Qs   = sm;                    // BQ * QP
    float* Ks   = Qs + BQ * QP;          // BKT * QP
    float* Vs   = Ks + BKT * QP;         // BKT * VP
    float* Ss   = Vs + BKT * VP;         // BQ * SP
    float* mrow = Ss + BQ * SP;          // BQ
    float* lrow = mrow + BQ;             // BQ
    float* arow = lrow + BQ;             // BQ

    int qb = blockIdx.x;
    int h  = blockIdx.y;
    int q0 = qb * BQ;
    int tid = threadIdx.x;
    int ty = tid >> 4;   // 0..15
    int tx = tid & 15;   // 0..15

    // load Q tile (rows q0..q0+63, 192 wide)
    for (int idx = tid; idx < BQ * DQK; idx += 256) {
        int r = idx / DQK, d = idx % DQK;
        Qs[r * QP + d] = g_q[(size_t)(q0 + r) * QDIM + h * DQK + d];
    }
    if (tid < BQ) { mrow[tid] = -1e30f; lrow[tid] = 0.f; }

    float acc[4][8];
#pragma unroll
    for (int i = 0; i < 4; i++)
#pragma unroll
        for (int j = 0; j < 8; j++) acc[i][j] = 0.f;
    __syncthreads();

    int nkb = qb + 1;
    for (int kb = 0; kb < nkb; kb++) {
        int k0 = kb * BKT;
        // load K tile: k_nope from g_kvb, k_pe from g_kpe
        for (int idx = tid; idx < BKT * DQK; idx += 256) {
            int r = idx / DQK, d = idx % DQK;
            int t = k0 + r;
            float v = (d < DN) ? g_kvb[(size_t)t * KVBDIM + h * 256 + d]
                               : g_kpe[(size_t)t * DR + (d - DN)];
            Ks[r * QP + d] = v;
        }
        // load V tile
        for (int idx = tid; idx < BKT * DV; idx += 256) {
            int r = idx / DV, d = idx % DV;
            Vs[r * VP + d] = g_kvb[(size_t)(k0 + r) * KVBDIM + h * 256 + DN + d];
        }
        __syncthreads();

        // S = Q @ K^T (4x4 microtile)
        float s[4][4];
#pragma unroll
        for (int i = 0; i < 4; i++)
#pragma unroll
            for (int j = 0; j < 4; j++) s[i][j] = 0.f;
        for (int d = 0; d < DQK; d += 4) {
            float4 qa[4], kv4[4];
#pragma unroll
            for (int i = 0; i < 4; i++) qa[i]  = *(float4*)(&Qs[(ty * 4 + i) * QP + d]);
#pragma unroll
            for (int j = 0; j < 4; j++) kv4[j] = *(float4*)(&Ks[(tx * 4 + j) * QP + d]);
#pragma unroll
            for (int i = 0; i < 4; i++)
#pragma unroll
                for (int j = 0; j < 4; j++) {
                    s[i][j] += qa[i].x * kv4[j].x + qa[i].y * kv4[j].y
                             + qa[i].z * kv4[j].z + qa[i].w * kv4[j].w;
                }
        }
        // scale + causal mask, write to Ss
#pragma unroll
        for (int i = 0; i < 4; i++) {
            int qi = q0 + ty * 4 + i;
#pragma unroll
            for (int j = 0; j < 4; j++) {
                int ki = k0 + tx * 4 + j;
                Ss[(ty * 4 + i) * SP + tx * 4 + j] =
                    (ki <= qi) ? s[i][j] * ATT_SCALE : -1e30f;
            }
        }
        __syncthreads();

        // online softmax per row (64 rows, one thread each)
        if (tid < BQ) {
            int r = tid;
            float m = mrow[r];
            float rmax = -1e30f;
#pragma unroll 8
            for (int c = 0; c < BKT; c++) rmax = fmaxf(rmax, Ss[r * SP + c]);
            float nm = fmaxf(m, rmax);
            float alpha = __expf(m - nm);
            float rsum = 0.f;
#pragma unroll 8
            for (int c = 0; c < BKT; c++) {
                float p = __expf(Ss[r * SP + c] - nm);
                Ss[r * SP + c] = p;
                rsum += p;
            }
            lrow[r] = lrow[r] * alpha + rsum;
            mrow[r] = nm;
            arow[r] = alpha;
        }
        __syncthreads();

        // rescale O, then O += P @ V (4x8 microtile over 64x128)
        float al[4];
#pragma unroll
        for (int i = 0; i < 4; i++) al[i] = arow[ty * 4 + i];
#pragma unroll
        for (int i = 0; i < 4; i++)
#pragma unroll
            for (int j = 0; j < 8; j++) acc[i][j] *= al[i];

        for (int kk = 0; kk < BKT; kk++) {
            float p[4];
            float4 v0 = *(float4*)(&Vs[kk * VP + tx * 8]);
            float4 v1 = *(float4*)(&Vs[kk * VP + tx * 8 + 4]);
#pragma unroll
            for (int i = 0; i < 4; i++) p[i] = Ss[(ty * 4 + i) * SP + kk];
#pragma unroll
            for (int i = 0; i < 4; i++) {
                acc[i][0] += p[i] * v0.x; acc[i][1] += p[i] * v0.y;
                acc[i][2] += p[i] * v0.z; acc[i][3] += p[i] * v0.w;
                acc[i][4] += p[i] * v1.x; acc[i][5] += p[i] * v1.y;
                acc[i][6] += p[i] * v1.z; acc[i][7] += p[i] * v1.w;
            }
        }
        __syncthreads();
    }

    // normalize and write out
#pragma unroll
    for (int i = 0; i < 4; i++) {
        int r = q0 + ty * 4 + i;
        float inv = 1.f / lrow[ty * 4 + i];
        float* op = g_attn + (size_t)r * ODIM + h * DV + tx * 8;
#pragma unroll
        for (int j = 0; j < 8; j++) op[j] = acc[i][j] * inv;
    }
}

// ---------------- launch ----------------------------------------------------
extern "C" void kernel_launch(void* const* d_in, const int* in_sizes, int n_in,
                              void* d_out, int out_size) {
    const int*   positions = (const int*)d_in[0];
    const float* hidden    = (const float*)d_in[1];
    const float* w_q       = (const float*)d_in[2];
    const float* w_kv_a    = (const float*)d_in[3];
    const float* kv_a_ln_w = (const float*)d_in[4];
    const float* w_kv_b    = (const float*)d_in[5];
    const float* w_o       = (const float*)d_in[6];
    float* out = (float*)d_out;

    float *p_q, *p_kv, *p_kvc, *p_kvb, *p_attn;
    cudaGetSymbolAddress((void**)&p_q,    g_q);
    cudaGetSymbolAddress((void**)&p_kv,   g_kv);
    cudaGetSymbolAddress((void**)&p_kvc,  g_kvc);
    cudaGetSymbolAddress((void**)&p_kvb,  g_kvb);
    cudaGetSymbolAddress((void**)&p_attn, g_attn);

    // 1. q = hidden @ w_q   [2048 x 3072]
    sgemm<<<dim3(QDIM / 128, T_TOK / 128), 256>>>(hidden, w_q, p_q, T_TOK, QDIM, HID);
    // 2. kv = hidden @ w_kv_a  [2048 x 576]
    sgemm<<<dim3((KVADIM + 127) / 128, T_TOK / 128), 256>>>(hidden, w_kv_a, p_kv, T_TOK, KVADIM, HID);
    // 3. rmsnorm + rope
    norm_rope<<<T_TOK, 256>>>(positions, kv_a_ln_w);
    // 4. kvb = kv_c @ w_kv_b  [2048 x 4096]
    sgemm<<<dim3(KVBDIM / 128, T_TOK / 128), 256>>>(p_kvc, w_kv_b, p_kvb, T_TOK, KVBDIM, KVD);
    // 5. attention
    size_t smem = (size_t)(BQ * QP + BKT * QP + BKT * VP + BQ * SP + 3 * BQ) * sizeof(float);
    cudaFuncSetAttribute(attn_kernel, cudaFuncAttributeMaxDynamicSharedMemorySize, (int)smem);
    attn_kernel<<<dim3(T_TOK / BQ, NH), 256, smem>>>();
    // 6. out = attn @ w_o  [2048 x 2048]
    sgemm<<<dim3(HID / 128, T_TOK / 128), 256>>>(p_attn, w_o, out, T_TOK, HID, ODIM);
}

// round 2
// speedup vs baseline: 2.0615x; 2.0615x over previous
#include <cuda_runtime.h>
#include <cuda_bf16.h>
#include <math.h>

// Problem constants
#define T_TOK 2048
#define HID   2048
#define NH    16
#define DN    128
#define DR    64
#define DV    128
#define KVD   512
#define DQK   192          // DN + DR
#define QDIM  (NH*DQK)     // 3072
#define KVADIM (KVD + DR)  // 576
#define KVBDIM (NH*(DN+DV)) // 4096
#define ODIM  (NH*DV)      // 2048
#define ATT_SCALE 0.07216878364870323f  // 1/sqrt(192)

// ---------------- scratch (device globals; no allocation allowed) ------------
__device__ float g_q[(size_t)T_TOK * QDIM];      // q (nope+pe), pe roped in place
__device__ float g_kv[(size_t)T_TOK * KVADIM];   // hs @ w_kv_a
__device__ float g_kvc[(size_t)T_TOK * KVD];     // rmsnormed latent
__device__ float g_kpe[(size_t)T_TOK * DR];      // roped k_pe
__device__ float g_kvb[(size_t)T_TOK * KVBDIM];  // kv_c @ w_kv_b  (per head: 128 k_nope | 128 v)
__device__ float g_attn[(size_t)T_TOK * ODIM];   // attention output

// ---------------- helpers ----------------------------------------------------
__device__ __forceinline__ unsigned f2tf(float x) {
    unsigned r;
    asm("cvt.rna.tf32.f32 %0, %1;" : "=r"(r) : "f"(x));
    return r;
}

__device__ __forceinline__ void mma_tf32(float& c0, float& c1, float& c2, float& c3,
                                         unsigned a0, unsigned a1, unsigned a2, unsigned a3,
                                         unsigned b0, unsigned b1) {
    asm volatile(
        "mma.sync.aligned.m16n8k8.row.col.f32.tf32.tf32.f32 "
        "{%0,%1,%2,%3}, {%4,%5,%6,%7}, {%8,%9}, {%0,%1,%2,%3};\n"
        : "+f"(c0), "+f"(c1), "+f"(c2), "+f"(c3)
        : "r"(a0), "r"(a1), "r"(a2), "r"(a3), "r"(b0), "r"(b1));
}

// ---------------- tf32 tensor-core GEMM: C[M,N] = A[M,K] @ B[K,N] -------------
// 128x128 tile, BK=32, 256 threads (8 warps, 2x4 warp grid, 64x32 per warp).
// M % 128 == 0, K % 32 == 0, N % 4 == 0 (partial N tiles guarded).
#define AP 36   // As pitch [m][k]
#define BP 136  // Bs pitch [k][n]

__global__ __launch_bounds__(256) void gemm_tf32(const float* __restrict__ A,
                                                 const float* __restrict__ B,
                                                 float* __restrict__ C,
                                                 int M, int N, int K) {
    __shared__ float As[128 * AP];
    __shared__ float Bs[32 * BP];
    const int tid = threadIdx.x;
    const int lane = tid & 31;
    const int wid = tid >> 5;
    const int g = lane >> 2;       // group 0..7
    const int tg = lane & 3;       // thread-in-group 0..3
    const int wm = wid & 1;        // 0..1
    const int wn = wid >> 1;       // 0..3
    const int crow = blockIdx.y * 128;
    const int ccol = blockIdx.x * 128;

    // global load mapping
    const int am = tid >> 3;            // 0..31 (A rows am + 32*i)
    const int ak = (tid & 7) << 2;      // 0..28
    const int bk = tid >> 5;            // 0..7  (B rows bk + 8*i)
    const int bn = (tid & 31) << 2;     // 0..124

    float4 pa[4], pb[4];
    float acc[4][4][4];
#pragma unroll
    for (int mt = 0; mt < 4; mt++)
#pragma unroll
        for (int nt = 0; nt < 4; nt++)
#pragma unroll
            for (int c = 0; c < 4; c++) acc[mt][nt][c] = 0.f;

    const unsigned* Asu = (const unsigned*)As;
    const unsigned* Bsu = (const unsigned*)Bs;

    // ---- prologue: load tile 0
#pragma unroll
    for (int i = 0; i < 4; i++)
        pa[i] = *(const float4*)(A + (size_t)(crow + am + 32 * i) * K + ak);
#pragma unroll
    for (int i = 0; i < 4; i++) {
        int col = ccol + bn;
        pb[i] = (col < N) ? *(const float4*)(B + (size_t)(bk + 8 * i) * N + col)
                          : make_float4(0.f, 0.f, 0.f, 0.f);
    }
    // store smem (with tf32 rounding)
#pragma unroll
    for (int i = 0; i < 4; i++) {
        uint4 u = make_uint4(f2tf(pa[i].x), f2tf(pa[i].y), f2tf(pa[i].z), f2tf(pa[i].w));
        *(uint4*)&As[(am + 32 * i) * AP + ak] = u;
        uint4 v = make_uint4(f2tf(pb[i].x), f2tf(pb[i].y), f2tf(pb[i].z), f2tf(pb[i].w));
        *(uint4*)&Bs[(bk + 8 * i) * BP + bn] = v;
    }
    __syncthreads();

    const int nk = K >> 5;
    for (int kt = 1; kt <= nk; kt++) {
        // prefetch next tile to registers
        if (kt < nk) {
            int k0 = kt << 5;
#pragma unroll
            for (int i = 0; i < 4; i++)
                pa[i] = *(const float4*)(A + (size_t)(crow + am + 32 * i) * K + k0 + ak);
#pragma unroll
            for (int i = 0; i < 4; i++) {
                int col = ccol + bn;
                pb[i] = (col < N) ? *(const float4*)(B + (size_t)(k0 + bk + 8 * i) * N + col)
                                  : make_float4(0.f, 0.f, 0.f, 0.f);
            }
        }
        // compute current tile from smem
#pragma unroll
        for (int ks = 0; ks < 4; ks++) {
            int k = ks << 3;
            unsigned af[4][4], bf[4][2];
#pragma unroll
            for (int mt = 0; mt < 4; mt++) {
                int m0 = wm * 64 + mt * 16;
                af[mt][0] = Asu[(m0 + g) * AP + k + tg];
                af[mt][1] = Asu[(m0 + 8 + g) * AP + k + tg];
                af[mt][2] = Asu[(m0 + g) * AP + k + tg + 4];
                af[mt][3] = Asu[(m0 + 8 + g) * AP + k + tg + 4];
            }
#pragma unroll
            for (int nt = 0; nt < 4; nt++) {
                int n0 = wn * 32 + nt * 8;
                bf[nt][0] = Bsu[(k + tg) * BP + n0 + g];
                bf[nt][1] = Bsu[(k + tg + 4) * BP + n0 + g];
            }
#pragma unroll
            for (int mt = 0; mt < 4; mt++)
#pragma unroll
                for (int nt = 0; nt < 4; nt++)
                    mma_tf32(acc[mt][nt][0], acc[mt][nt][1], acc[mt][nt][2], acc[mt][nt][3],
                             af[mt][0], af[mt][1], af[mt][2], af[mt][3],
                             bf[nt][0], bf[nt][1]);
        }
        if (kt < nk) {
            __syncthreads();
#pragma unroll
            for (int i = 0; i < 4; i++) {
                uint4 u = make_uint4(f2tf(pa[i].x), f2tf(pa[i].y), f2tf(pa[i].z), f2tf(pa[i].w));
                *(uint4*)&As[(am + 32 * i) * AP + ak] = u;
                uint4 v = make_uint4(f2tf(pb[i].x), f2tf(pb[i].y), f2tf(pb[i].z), f2tf(pb[i].w));
                *(uint4*)&Bs[(bk + 8 * i) * BP + bn] = v;
            }
            __syncthreads();
        }
    }

    // store C
#pragma unroll
    for (int mt = 0; mt < 4; mt++) {
        int row = crow + wm * 64 + mt * 16 + g;
#pragma unroll
        for (int nt = 0; nt < 4; nt++) {
            int col = ccol + wn * 32 + nt * 8 + tg * 2;
            if (col < N) {
                *(float2*)(C + (size_t)row * N + col) =
                    make_float2(acc[mt][nt][0], acc[mt][nt][1]);
                *(float2*)(C + (size_t)(row + 8) * N + col) =
                    make_float2(acc[mt][nt][2], acc[mt][nt][3]);
            }
        }
    }
}

// ---------------- RMSNorm (kv latent) + RoPE (q_pe inplace, k_pe) ------------
__global__ __launch_bounds__(256) void norm_rope(const int* __restrict__ positions,
                                                 const float* __restrict__ lnw) {
    int t   = blockIdx.x;
    int tid = threadIdx.x;
    const float* kvrow = g_kv + (size_t)t * KVADIM;

    float ss = 0.f;
    for (int i = tid; i < KVD; i += 256) {
        float v = kvrow[i];
        ss += v * v;
    }
#pragma unroll
    for (int o = 16; o > 0; o >>= 1) ss += __shfl_xor_sync(0xFFFFFFFFu, ss, o);
    __shared__ float red[8];
    if ((tid & 31) == 0) red[tid >> 5] = ss;
    __syncthreads();
    float tot = 0.f;
#pragma unroll
    for (int w = 0; w < 8; w++) tot += red[w];
    float inv = rsqrtf(tot * (1.f / KVD) + 1e-6f);

    for (int i = tid; i < KVD; i += 256)
        g_kvc[(size_t)t * KVD + i] = kvrow[i] * inv * lnw[i];

    float pos = (float)positions[t];

    for (int i = tid; i < DR / 2; i += 256) {
        float invf = (float)exp(-((double)(2 * i) / (double)DR) * 9.210340371976184);
        float f = pos * invf;
        float c = cosf(f), s = sinf(f);
        float x1 = kvrow[KVD + 2 * i];
        float x2 = kvrow[KVD + 2 * i + 1];
        g_kpe[(size_t)t * DR + 2 * i]     = x1 * c - x2 * s;
        g_kpe[(size_t)t * DR + 2 * i + 1] = x2 * c + x1 * s;
    }

    for (int idx = tid; idx < NH * (DR / 2); idx += 256) {
        int h = idx / (DR / 2);
        int i = idx % (DR / 2);
        float invf = (float)exp(-((double)(2 * i) / (double)DR) * 9.210340371976184);
        float f = pos * invf;
        float c = cosf(f), s = sinf(f);
        float* qp = g_q + (size_t)t * QDIM + h * DQK + DN + 2 * i;
        float x1 = qp[0], x2 = qp[1];
        qp[0] = x1 * c - x2 * s;
        qp[1] = x2 * c + x1 * s;
    }
}

// ---------------- flash attention, fp32 FFMA, BQ=BK=64 -----------------------
// In-register online softmax (rows live in one 16-lane half-warp).
#define BQ 64
#define BKT 64
#define QP 196   // Q/K pitch
#define VP 132   // V pitch
#define SP 68    // P pitch

__global__ __launch_bounds__(256) void attn_kernel() {
    extern __shared__ float sm[];
    float* Qs = sm;                    // BQ * QP
    float* Ks = Qs + BQ * QP;          // BKT * QP
    float* Vs = Ks + BKT * QP;         // BKT * VP
    float* Ss = Vs + BKT * VP;         // BQ * SP

    int qb = blockIdx.x;
    int h  = blockIdx.y;
    int q0 = qb * BQ;
    int tid = threadIdx.x;
    int ty = tid >> 4;   // 0..15 : row group (rows ty*4..ty*4+3)
    int tx = tid & 15;   // 0..15 : column lane

    // load Q tile
    for (int idx = tid; idx < BQ * DQK; idx += 256) {
        int r = idx / DQK, d = idx % DQK;
        Qs[r * QP + d] = g_q[(size_t)(q0 + r) * QDIM + h * DQK + d];
    }

    float m_i[4], l_i[4];
#pragma unroll
    for (int i = 0; i < 4; i++) { m_i[i] = -1e30f; l_i[i] = 0.f; }

    float acc[4][8];
#pragma unroll
    for (int i = 0; i < 4; i++)
#pragma unroll
        for (int j = 0; j < 8; j++) acc[i][j] = 0.f;
    __syncthreads();

    int nkb = qb + 1;
    for (int kb = 0; kb < nkb; kb++) {
        int k0 = kb * BKT;
        // load K tile (k_nope | k_pe)
        for (int idx = tid; idx < BKT * DQK; idx += 256) {
            int r = idx / DQK, d = idx % DQK;
            int t = k0 + r;
            float v = (d < DN) ? g_kvb[(size_t)t * KVBDIM + h * 256 + d]
                               : g_kpe[(size_t)t * DR + (d - DN)];
            Ks[r * QP + d] = v;
        }
        // load V tile
        for (int idx = tid; idx < BKT * DV; idx += 256) {
            int r = idx / DV, d = idx % DV;
            Vs[r * VP + d] = g_kvb[(size_t)(k0 + r) * KVBDIM + h * 256 + DN + d];
        }
        __syncthreads();

        // S = Q @ K^T ; thread (ty,tx) covers rows ty*4+i, cols 16*j+tx
        float s[4][4];
#pragma unroll
        for (int i = 0; i < 4; i++)
#pragma unroll
            for (int j = 0; j < 4; j++) s[i][j] = 0.f;
        for (int d = 0; d < DQK; d += 4) {
            float4 qa[4], kv4[4];
#pragma unroll
            for (int i = 0; i < 4; i++) qa[i]  = *(float4*)(&Qs[(ty * 4 + i) * QP + d]);
#pragma unroll
            for (int j = 0; j < 4; j++) kv4[j] = *(float4*)(&Ks[(j * 16 + tx) * QP + d]);
#pragma unroll
            for (int i = 0; i < 4; i++)
#pragma unroll
                for (int j = 0; j < 4; j++) {
                    s[i][j] += qa[i].x * kv4[j].x + qa[i].y * kv4[j].y
                             + qa[i].z * kv4[j].z + qa[i].w * kv4[j].w;
                }
        }

        // scale + causal mask
#pragma unroll
        for (int i = 0; i < 4; i++) {
            int qi = q0 + ty * 4 + i;
#pragma unroll
            for (int j = 0; j < 4; j++) {
                int ki = k0 + j * 16 + tx;
                s[i][j] = (ki <= qi) ? s[i][j] * ATT_SCALE : -1e30f;
            }
        }

        // in-register online softmax (reduce across the 16-lane half-warp)
#pragma unroll
        for (int i = 0; i < 4; i++) {
            float rmax = fmaxf(fmaxf(s[i][0], s[i][1]), fmaxf(s[i][2], s[i][3]));
#pragma unroll
            for (int o = 8; o > 0; o >>= 1)
                rmax = fmaxf(rmax, __shfl_xor_sync(0xFFFFFFFFu, rmax, o));
            float nm = fmaxf(m_i[i], rmax);
            float alpha = __expf(m_i[i] - nm);
            m_i[i] = nm;
            float rs = 0.f;
#pragma unroll
            for (int j = 0; j < 4; j++) {
                float p = __expf(s[i][j] - nm);
                s[i][j] = p;
                rs += p;
            }
#pragma unroll
            for (int o = 8; o > 0; o >>= 1)
                rs += __shfl_xor_sync(0xFFFFFFFFu, rs, o);
            l_i[i] = l_i[i] * alpha + rs;
#pragma unroll
            for (int j = 0; j < 8; j++) acc[i][j] *= alpha;
            // write P row fragment (scattered cols 16*j+tx -> conflict-free)
#pragma unroll
            for (int j = 0; j < 4; j++)
                Ss[(ty * 4 + i) * SP + j * 16 + tx] = s[i][j];
        }
        __syncthreads();

        // O += P @ V ; thread covers V cols {tx*4..tx*4+3, 64+tx*4..64+tx*4+3}
        for (int kk = 0; kk < BKT; kk++) {
            float4 v0 = *(float4*)(&Vs[kk * VP + tx * 4]);
            float4 v1 = *(float4*)(&Vs[kk * VP + 64 + tx * 4]);
            float p[4];
#pragma unroll
            for (int i = 0; i < 4; i++) p[i] = Ss[(ty * 4 + i) * SP + kk];
#pragma unroll
            for (int i = 0; i < 4; i++) {
                acc[i][0] += p[i] * v0.x; acc[i][1] += p[i] * v0.y;
                acc[i][2] += p[i] * v0.z; acc[i][3] += p[i] * v0.w;
                acc[i][4] += p[i] * v1.x; acc[i][5] += p[i] * v1.y;
                acc[i][6] += p[i] * v1.z; acc[i][7] += p[i] * v1.w;
            }
        }
        __syncthreads();
    }

    // normalize and write out (cols tx*4 and 64+tx*4)
#pragma unroll
    for (int i = 0; i < 4; i++) {
        int r = q0 + ty * 4 + i;
        float inv = 1.f / l_i[i];
        float* op = g_attn + (size_t)r * ODIM + h * DV;
        *(float4*)(op + tx * 4) =
            make_float4(acc[i][0] * inv, acc[i][1] * inv, acc[i][2] * inv, acc[i][3] * inv);
        *(float4*)(op + 64 + tx * 4) =
            make_float4(acc[i][4] * inv, acc[i][5] * inv, acc[i][6] * inv, acc[i][7] * inv);
    }
}

// ---------------- launch ----------------------------------------------------
extern "C" void kernel_launch(void* const* d_in, const int* in_sizes, int n_in,
                              void* d_out, int out_size) {
    const int*   positions = (const int*)d_in[0];
    const float* hidden    = (const float*)d_in[1];
    const float* w_q       = (const float*)d_in[2];
    const float* w_kv_a    = (const float*)d_in[3];
    const float* kv_a_ln_w = (const float*)d_in[4];
    const float* w_kv_b    = (const float*)d_in[5];
    const float* w_o       = (const float*)d_in[6];
    float* out = (float*)d_out;

    float *p_q, *p_kv, *p_kvc, *p_kvb, *p_attn;
    cudaGetSymbolAddress((void**)&p_q,    g_q);
    cudaGetSymbolAddress((void**)&p_kv,   g_kv);
    cudaGetSymbolAddress((void**)&p_kvc,  g_kvc);
    cudaGetSymbolAddress((void**)&p_kvb,  g_kvb);
    cudaGetSymbolAddress((void**)&p_attn, g_attn);

    // 1. q = hidden @ w_q   [2048 x 3072]
    gemm_tf32<<<dim3(QDIM / 128, T_TOK / 128), 256>>>(hidden, w_q, p_q, T_TOK, QDIM, HID);
    // 2. kv = hidden @ w_kv_a  [2048 x 576]
    gemm_tf32<<<dim3((KVADIM + 127) / 128, T_TOK / 128), 256>>>(hidden, w_kv_a, p_kv, T_TOK, KVADIM, HID);
    // 3. rmsnorm + rope
    norm_rope<<<T_TOK, 256>>>(positions, kv_a_ln_w);
    // 4. kvb = kv_c @ w_kv_b  [2048 x 4096]
    gemm_tf32<<<dim3(KVBDIM / 128, T_TOK / 128), 256>>>(p_kvc, w_kv_b, p_kvb, T_TOK, KVBDIM, KVD);
    // 5. attention
    size_t smem = (size_t)(BQ * QP + BKT * QP + BKT * VP + BQ * SP) * sizeof(float);
    cudaFuncSetAttribute(attn_kernel, cudaFuncAttributeMaxDynamicSharedMemorySize, (int)smem);
    attn_kernel<<<dim3(T_TOK / BQ, NH), 256, smem>>>();
    // 6. out = attn @ w_o  [2048 x 2048]
    gemm_tf32<<<dim3(HID / 128, T_TOK / 128), 256>>>(p_attn, w_o, out, T_TOK, HID, ODIM);
}

// round 3
// speedup vs baseline: 4.4136x; 2.1409x over previous
#include <cuda_runtime.h>
#include <cuda_bf16.h>
#include <math.h>

// Problem constants
#define T_TOK 2048
#define HID   2048
#define NH    16
#define DN    128
#define DR    64
#define DV    128
#define KVD   512
#define DQK   192          // DN + DR
#define QDIM  (NH*DQK)     // 3072
#define KVADIM (KVD + DR)  // 576
#define KVBDIM (NH*(DN+DV)) // 4096
#define ODIM  (NH*DV)      // 2048
#define ATT_SCALE 0.07216878364870323f  // 1/sqrt(192)

// ---------------- scratch (device globals; no allocation allowed) ------------
__device__ float g_q[(size_t)T_TOK * QDIM];
__device__ float g_kv[(size_t)T_TOK * KVADIM];
__device__ float g_kvc[(size_t)T_TOK * KVD];
__device__ float g_kpe[(size_t)T_TOK * DR];
__device__ float g_kvb[(size_t)T_TOK * KVBDIM];
__device__ float g_attn[(size_t)T_TOK * ODIM];

// ---------------- helpers ----------------------------------------------------
__device__ __forceinline__ unsigned f2tf(float x) {
    unsigned r;
    asm("cvt.rna.tf32.f32 %0, %1;" : "=r"(r) : "f"(x));
    return r;
}

__device__ __forceinline__ void mma_tf32(float& c0, float& c1, float& c2, float& c3,
                                         unsigned a0, unsigned a1, unsigned a2, unsigned a3,
                                         unsigned b0, unsigned b1) {
    asm volatile(
        "mma.sync.aligned.m16n8k8.row.col.f32.tf32.tf32.f32 "
        "{%0,%1,%2,%3}, {%4,%5,%6,%7}, {%8,%9}, {%0,%1,%2,%3};\n"
        : "+f"(c0), "+f"(c1), "+f"(c2), "+f"(c3)
        : "r"(a0), "r"(a1), "r"(a2), "r"(a3), "r"(b0), "r"(b1));
}

// ---------------- tf32 tensor-core GEMM: C[M,N] = A[M,K] @ B[K,N] -------------
#define AP 36   // As pitch [m][k]
#define BP 136  // Bs pitch [k][n]

__global__ __launch_bounds__(256, 2) void gemm_tf32(const float* __restrict__ A,
                                                    const float* __restrict__ B,
                                                    float* __restrict__ C,
                                                    int M, int N, int K) {
    __shared__ float As[128 * AP];
    __shared__ float Bs[32 * BP];
    const int tid = threadIdx.x;
    const int lane = tid & 31;
    const int wid = tid >> 5;
    const int g = lane >> 2;
    const int tg = lane & 3;
    const int wm = wid & 1;
    const int wn = wid >> 1;
    const int crow = blockIdx.y * 128;
    const int ccol = blockIdx.x * 128;

    const int am = tid >> 3;
    const int ak = (tid & 7) << 2;
    const int bk = tid >> 5;
    const int bn = (tid & 31) << 2;

    float4 pa[4], pb[4];
    float acc[4][4][4];
#pragma unroll
    for (int mt = 0; mt < 4; mt++)
#pragma unroll
        for (int nt = 0; nt < 4; nt++)
#pragma unroll
            for (int c = 0; c < 4; c++) acc[mt][nt][c] = 0.f;

    const unsigned* Asu = (const unsigned*)As;
    const unsigned* Bsu = (const unsigned*)Bs;

#pragma unroll
    for (int i = 0; i < 4; i++)
        pa[i] = *(const float4*)(A + (size_t)(crow + am + 32 * i) * K + ak);
#pragma unroll
    for (int i = 0; i < 4; i++) {
        int col = ccol + bn;
        pb[i] = (col < N) ? *(const float4*)(B + (size_t)(bk + 8 * i) * N + col)
                          : make_float4(0.f, 0.f, 0.f, 0.f);
    }
#pragma unroll
    for (int i = 0; i < 4; i++) {
        uint4 u = make_uint4(f2tf(pa[i].x), f2tf(pa[i].y), f2tf(pa[i].z), f2tf(pa[i].w));
        *(uint4*)&As[(am + 32 * i) * AP + ak] = u;
        uint4 v = make_uint4(f2tf(pb[i].x), f2tf(pb[i].y), f2tf(pb[i].z), f2tf(pb[i].w));
        *(uint4*)&Bs[(bk + 8 * i) * BP + bn] = v;
    }
    __syncthreads();

    const int nk = K >> 5;
    for (int kt = 1; kt <= nk; kt++) {
        if (kt < nk) {
            int k0 = kt << 5;
#pragma unroll
            for (int i = 0; i < 4; i++)
                pa[i] = *(const float4*)(A + (size_t)(crow + am + 32 * i) * K + k0 + ak);
#pragma unroll
            for (int i = 0; i < 4; i++) {
                int col = ccol + bn;
                pb[i] = (col < N) ? *(const float4*)(B + (size_t)(k0 + bk + 8 * i) * N + col)
                                  : make_float4(0.f, 0.f, 0.f, 0.f);
            }
        }
#pragma unroll
        for (int ks = 0; ks < 4; ks++) {
            int k = ks << 3;
            unsigned af[4][4], bf[4][2];
#pragma unroll
            for (int mt = 0; mt < 4; mt++) {
                int m0 = wm * 64 + mt * 16;
                af[mt][0] = Asu[(m0 + g) * AP + k + tg];
                af[mt][1] = Asu[(m0 + 8 + g) * AP + k + tg];
                af[mt][2] = Asu[(m0 + g) * AP + k + tg + 4];
                af[mt][3] = Asu[(m0 + 8 + g) * AP + k + tg + 4];
            }
#pragma unroll
            for (int nt = 0; nt < 4; nt++) {
                int n0 = wn * 32 + nt * 8;
                bf[nt][0] = Bsu[(k + tg) * BP + n0 + g];
                bf[nt][1] = Bsu[(k + tg + 4) * BP + n0 + g];
            }
#pragma unroll
            for (int mt = 0; mt < 4; mt++)
#pragma unroll
                for (int nt = 0; nt < 4; nt++)
                    mma_tf32(acc[mt][nt][0], acc[mt][nt][1], acc[mt][nt][2], acc[mt][nt][3],
                             af[mt][0], af[mt][1], af[mt][2], af[mt][3],
                             bf[nt][0], bf[nt][1]);
        }
        if (kt < nk) {
            __syncthreads();
#pragma unroll
            for (int i = 0; i < 4; i++) {
                uint4 u = make_uint4(f2tf(pa[i].x), f2tf(pa[i].y), f2tf(pa[i].z), f2tf(pa[i].w));
                *(uint4*)&As[(am + 32 * i) * AP + ak] = u;
                uint4 v = make_uint4(f2tf(pb[i].x), f2tf(pb[i].y), f2tf(pb[i].z), f2tf(pb[i].w));
                *(uint4*)&Bs[(bk + 8 * i) * BP + bn] = v;
            }
            __syncthreads();
        }
    }

#pragma unroll
    for (int mt = 0; mt < 4; mt++) {
        int row = crow + wm * 64 + mt * 16 + g;
#pragma unroll
        for (int nt = 0; nt < 4; nt++) {
            int col = ccol + wn * 32 + nt * 8 + tg * 2;
            if (col < N) {
                *(float2*)(C + (size_t)row * N + col) =
                    make_float2(acc[mt][nt][0], acc[mt][nt][1]);
                *(float2*)(C + (size_t)(row + 8) * N + col) =
                    make_float2(acc[mt][nt][2], acc[mt][nt][3]);
            }
        }
    }
}

// ---------------- RMSNorm + RoPE ---------------------------------------------
__global__ __launch_bounds__(256) void norm_rope(const int* __restrict__ positions,
                                                 const float* __restrict__ lnw) {
    int t   = blockIdx.x;
    int tid = threadIdx.x;
    const float* kvrow = g_kv + (size_t)t * KVADIM;

    float ss = 0.f;
    for (int i = tid; i < KVD; i += 256) {
        float v = kvrow[i];
        ss += v * v;
    }
#pragma unroll
    for (int o = 16; o > 0; o >>= 1) ss += __shfl_xor_sync(0xFFFFFFFFu, ss, o);
    __shared__ float red[8];
    if ((tid & 31) == 0) red[tid >> 5] = ss;
    __syncthreads();
    float tot = 0.f;
#pragma unroll
    for (int w = 0; w < 8; w++) tot += red[w];
    float inv = rsqrtf(tot * (1.f / KVD) + 1e-6f);

    for (int i = tid; i < KVD; i += 256)
        g_kvc[(size_t)t * KVD + i] = kvrow[i] * inv * lnw[i];

    float pos = (float)positions[t];

    for (int i = tid; i < DR / 2; i += 256) {
        float invf = (float)exp(-((double)(2 * i) / (double)DR) * 9.210340371976184);
        float f = pos * invf;
        float c = cosf(f), s = sinf(f);
        float x1 = kvrow[KVD + 2 * i];
        float x2 = kvrow[KVD + 2 * i + 1];
        g_kpe[(size_t)t * DR + 2 * i]     = x1 * c - x2 * s;
        g_kpe[(size_t)t * DR + 2 * i + 1] = x2 * c + x1 * s;
    }

    for (int idx = tid; idx < NH * (DR / 2); idx += 256) {
        int h = idx / (DR / 2);
        int i = idx % (DR / 2);
        float invf = (float)exp(-((double)(2 * i) / (double)DR) * 9.210340371976184);
        float f = pos * invf;
        float c = cosf(f), s = sinf(f);
        float* qp = g_q + (size_t)t * QDIM + h * DQK + DN + 2 * i;
        float x1 = qp[0], x2 = qp[1];
        qp[0] = x1 * c - x2 * s;
        qp[1] = x2 * c + x1 * s;
    }
}

// ---------------- flash attention, tf32 mma, BQ=128, BK=64 -------------------
#define BQ 128
#define BKT 64
#define QP 196   // Q/K pitch: 196 % 32 == 4 -> fragment LDS banks g*4+tg (conflict-free)
#define VP 132   // V pitch:   132 % 32 == 4
#define PP 68    // P pitch:    68 % 32 == 4

__global__ __launch_bounds__(256, 1) void attn_kernel() {
    extern __shared__ float sm[];
    float* Qs = sm;                       // BQ*QP
    float* Ks = Qs + BQ * QP;             // BKT*QP
    float* Vs = Ks + BKT * QP;            // BKT*VP
    float* Ps = Vs + BKT * VP;            // BQ*PP

    const int bid = blockIdx.x;
    const int qb = bid & 15;
    const int h  = bid >> 4;
    const int q0 = qb * BQ;
    const int tid = threadIdx.x;
    const int lane = tid & 31;
    const int wid = tid >> 5;
    const int g = lane >> 2;
    const int tg = lane & 3;
    const int m0 = wid * 16;

    const unsigned* Qsu = (const unsigned*)Qs;
    const unsigned* Ksu = (const unsigned*)Ks;
    const unsigned* Vsu = (const unsigned*)Vs;
    const unsigned* Psu = (const unsigned*)Ps;

    // load Q tile as tf32
    for (int idx = tid; idx < BQ * 48; idx += 256) {
        int r = idx / 48, c = idx % 48;
        float4 v = *(const float4*)(g_q + (size_t)(q0 + r) * QDIM + h * DQK + c * 4);
        uint4 u = make_uint4(f2tf(v.x), f2tf(v.y), f2tf(v.z), f2tf(v.w));
        *(uint4*)&Qs[r * QP + c * 4] = u;
    }

    float m_i[2] = {-1e30f, -1e30f};
    float l_i[2] = {0.f, 0.f};
    float oacc[16][4];
#pragma unroll
    for (int nt = 0; nt < 16; nt++)
#pragma unroll
        for (int c = 0; c < 4; c++) oacc[nt][c] = 0.f;

    const int r0 = q0 + m0 + g;
    const int r1 = r0 + 8;
    const int nkb = qb * 2 + 2;

    for (int kb = 0; kb < nkb; kb++) {
        int k0 = kb * BKT;
        __syncthreads();   // prev tile fully consumed

        // K tile (k_nope | k_pe), tf32
        for (int idx = tid; idx < BKT * 48; idx += 256) {
            int r = idx / 48, c = idx % 48;
            float4 v;
            if (c < 32)
                v = *(const float4*)(g_kvb + (size_t)(k0 + r) * KVBDIM + h * 256 + c * 4);
            else
                v = *(const float4*)(g_kpe + (size_t)(k0 + r) * DR + (c - 32) * 4);
            uint4 u = make_uint4(f2tf(v.x), f2tf(v.y), f2tf(v.z), f2tf(v.w));
            *(uint4*)&Ks[r * QP + c * 4] = u;
        }
        // V tile, tf32
        for (int idx = tid; idx < BKT * 32; idx += 256) {
            int r = idx >> 5, c = idx & 31;
            float4 v = *(const float4*)(g_kvb + (size_t)(k0 + r) * KVBDIM + h * 256 + DN + c * 4);
            uint4 u = make_uint4(f2tf(v.x), f2tf(v.y), f2tf(v.z), f2tf(v.w));
            *(uint4*)&Vs[r * VP + c * 4] = u;
        }
        __syncthreads();

        // S = Q @ K^T : warp computes rows m0..m0+15, cols 0..63
        float sacc[8][4];
#pragma unroll
        for (int nt = 0; nt < 8; nt++)
#pragma unroll
            for (int c = 0; c < 4; c++) sacc[nt][c] = 0.f;

#pragma unroll
        for (int ks = 0; ks < 24; ks++) {
            int k = ks * 8;
            unsigned a0 = Qsu[(m0 + g) * QP + k + tg];
            unsigned a1 = Qsu[(m0 + 8 + g) * QP + k + tg];
            unsigned a2 = Qsu[(m0 + g) * QP + k + tg + 4];
            unsigned a3 = Qsu[(m0 + 8 + g) * QP + k + tg + 4];
#pragma unroll
            for (int nt = 0; nt < 8; nt++) {
                unsigned b0 = Ksu[(nt * 8 + g) * QP + k + tg];
                unsigned b1 = Ksu[(nt * 8 + g) * QP + k + tg + 4];
                mma_tf32(sacc[nt][0], sacc[nt][1], sacc[nt][2], sacc[nt][3],
                         a0, a1, a2, a3, b0, b1);
            }
        }

        // scale + causal mask
#pragma unroll
        for (int nt = 0; nt < 8; nt++) {
            int c0i = k0 + nt * 8 + tg * 2;
            sacc[nt][0] = (c0i     <= r0) ? sacc[nt][0] * ATT_SCALE : -1e30f;
            sacc[nt][1] = (c0i + 1 <= r0) ? sacc[nt][1] * ATT_SCALE : -1e30f;
            sacc[nt][2] = (c0i     <= r1) ? sacc[nt][2] * ATT_SCALE : -1e30f;
            sacc[nt][3] = (c0i + 1 <= r1) ? sacc[nt][3] * ATT_SCALE : -1e30f;
        }

        // online softmax (rows r0, r1); reduce across quad (lanes share g)
        float mx0 = -1e30f, mx1 = -1e30f;
#pragma unroll
        for (int nt = 0; nt < 8; nt++) {
            mx0 = fmaxf(mx0, fmaxf(sacc[nt][0], sacc[nt][1]));
            mx1 = fmaxf(mx1, fmaxf(sacc[nt][2], sacc[nt][3]));
        }
        mx0 = fmaxf(mx0, __shfl_xor_sync(0xFFFFFFFFu, mx0, 1));
        mx0 = fmaxf(mx0, __shfl_xor_sync(0xFFFFFFFFu, mx0, 2));
        mx1 = fmaxf(mx1, __shfl_xor_sync(0xFFFFFFFFu, mx1, 1));
        mx1 = fmaxf(mx1, __shfl_xor_sync(0xFFFFFFFFu, mx1, 2));

        float nm0 = fmaxf(m_i[0], mx0);
        float nm1 = fmaxf(m_i[1], mx1);
        float al0 = __expf(m_i[0] - nm0);
        float al1 = __expf(m_i[1] - nm1);
        m_i[0] = nm0; m_i[1] = nm1;

        float rs0 = 0.f, rs1 = 0.f;
#pragma unroll
        for (int nt = 0; nt < 8; nt++) {
            float p0 = __expf(sacc[nt][0] - nm0);
            float p1 = __expf(sacc[nt][1] - nm0);
            float p2 = __expf(sacc[nt][2] - nm1);
            float p3 = __expf(sacc[nt][3] - nm1);
            sacc[nt][0] = p0; sacc[nt][1] = p1; sacc[nt][2] = p2; sacc[nt][3] = p3;
            rs0 += p0 + p1; rs1 += p2 + p3;
        }
        rs0 += __shfl_xor_sync(0xFFFFFFFFu, rs0, 1);
        rs0 += __shfl_xor_sync(0xFFFFFFFFu, rs0, 2);
        rs1 += __shfl_xor_sync(0xFFFFFFFFu, rs1, 1);
        rs1 += __shfl_xor_sync(0xFFFFFFFFu, rs1, 2);
        l_i[0] = l_i[0] * al0 + rs0;
        l_i[1] = l_i[1] * al1 + rs1;

        // rescale O
#pragma unroll
        for (int nt = 0; nt < 16; nt++) {
            oacc[nt][0] *= al0; oacc[nt][1] *= al0;
            oacc[nt][2] *= al1; oacc[nt][3] *= al1;
        }

        // store P (tf32) — warp-private rows, only __syncwarp needed
#pragma unroll
        for (int nt = 0; nt < 8; nt++) {
            int col = nt * 8 + tg * 2;
            uint2 u0 = make_uint2(f2tf(sacc[nt][0]), f2tf(sacc[nt][1]));
            uint2 u1 = make_uint2(f2tf(sacc[nt][2]), f2tf(sacc[nt][3]));
            *(uint2*)&Ps[(m0 + g) * PP + col]     = u0;
            *(uint2*)&Ps[(m0 + 8 + g) * PP + col] = u1;
        }
        __syncwarp();

        // O += P @ V
#pragma unroll
        for (int ks = 0; ks < 8; ks++) {
            int k = ks * 8;
            unsigned a0 = Psu[(m0 + g) * PP + k + tg];
            unsigned a1 = Psu[(m0 + 8 + g) * PP + k + tg];
            unsigned a2 = Psu[(m0 + g) * PP + k + tg + 4];
            unsigned a3 = Psu[(m0 + 8 + g) * PP + k + tg + 4];
#pragma unroll
            for (int nt = 0; nt < 16; nt++) {
                unsigned b0 = Vsu[(k + tg) * VP + nt * 8 + g];
                unsigned b1 = Vsu[(k + tg + 4) * VP + nt * 8 + g];
                mma_tf32(oacc[nt][0], oacc[nt][1], oacc[nt][2], oacc[nt][3],
                         a0, a1, a2, a3, b0, b1);
            }
        }
    }

    // normalize and write out
    float inv0 = 1.f / l_i[0];
    float inv1 = 1.f / l_i[1];
#pragma unroll
    for (int nt = 0; nt < 16; nt++) {
        int col = nt * 8 + tg * 2;
        *(float2*)&g_attn[(size_t)r0 * ODIM + h * DV + col] =
            make_float2(oacc[nt][0] * inv0, oacc[nt][1] * inv0);
        *(float2*)&g_attn[(size_t)r1 * ODIM + h * DV + col] =
            make_float2(oacc[nt][2] * inv1, oacc[nt][3] * inv1);
    }
}

// ---------------- launch ----------------------------------------------------
extern "C" void kernel_launch(void* const* d_in, const int* in_sizes, int n_in,
                              void* d_out, int out_size) {
    const int*   positions = (const int*)d_in[0];
    const float* hidden    = (const float*)d_in[1];
    const float* w_q       = (const float*)d_in[2];
    const float* w_kv_a    = (const float*)d_in[3];
    const float* kv_a_ln_w = (const float*)d_in[4];
    const float* w_kv_b    = (const float*)d_in[5];
    const float* w_o       = (const float*)d_in[6];
    float* out = (float*)d_out;

    float *p_q, *p_kv, *p_kvc, *p_kvb, *p_attn;
    cudaGetSymbolAddress((void**)&p_q,    g_q);
    cudaGetSymbolAddress((void**)&p_kv,   g_kv);
    cudaGetSymbolAddress((void**)&p_kvc,  g_kvc);
    cudaGetSymbolAddress((void**)&p_kvb,  g_kvb);
    cudaGetSymbolAddress((void**)&p_attn, g_attn);

    gemm_tf32<<<dim3(QDIM / 128, T_TOK / 128), 256>>>(hidden, w_q, p_q, T_TOK, QDIM, HID);
    gemm_tf32<<<dim3((KVADIM + 127) / 128, T_TOK / 128), 256>>>(hidden, w_kv_a, p_kv, T_TOK, KVADIM, HID);
    norm_rope<<<T_TOK, 256>>>(positions, kv_a_ln_w);
    gemm_tf32<<<dim3(KVBDIM / 128, T_TOK / 128), 256>>>(p_kvc, w_kv_b, p_kvb, T_TOK, KVBDIM, KVD);

    size_t smem = (size_t)(BQ * QP + BKT * QP + BKT * VP + BQ * PP) * sizeof(float);
    cudaFuncSetAttribute(attn_kernel, cudaFuncAttributeMaxDynamicSharedMemorySize, (int)smem);
    attn_kernel<<<T_TOK / BQ * NH, 256, smem>>>();

    gemm_tf32<<<dim3(HID / 128, T_TOK / 128), 256>>>(p_attn, w_o, out, T_TOK, HID, ODIM);
}

// round 5
// speedup vs baseline: 5.3322x; 1.2081x over previous
#include <cuda_runtime.h>
#include <cuda_bf16.h>
#include <cstdint>
#include <math.h>

// Problem constants
#define T_TOK 2048
#define HID   2048
#define NH    16
#define DN    128
#define DR    64
#define DV    128
#define KVD   512
#define DQK   192
#define QDIM  (NH*DQK)      // 3072
#define KVADIM (KVD + DR)   // 576
#define KVBDIM (NH*(DN+DV)) // 4096
#define ODIM  (NH*DV)       // 2048
#define ATT_SCALE 0.07216878364870323f

// ---------------- scratch ----------------------------------------------------
__device__ float g_q[(size_t)T_TOK * QDIM];
__device__ float g_kv[(size_t)T_TOK * KVADIM];
__device__ float g_kvc[(size_t)T_TOK * KVD];
__device__ float g_kpe[(size_t)T_TOK * DR];
__device__ float g_kvb[(size_t)T_TOK * KVBDIM];
__device__ float g_attn[(size_t)T_TOK * ODIM];
// tf32-pre-rounded inputs
__device__ float g_hid[(size_t)T_TOK * HID];
__device__ float g_wq[(size_t)HID * QDIM];
__device__ float g_wkva[(size_t)HID * KVADIM];
__device__ float g_wkvb[(size_t)KVD * KVBDIM];
__device__ float g_wo[(size_t)ODIM * HID];

// ---------------- helpers ----------------------------------------------------
__device__ __forceinline__ unsigned f2tf(float x) {
    unsigned r;
    asm("cvt.rna.tf32.f32 %0, %1;" : "=r"(r) : "f"(x));
    return r;
}
__device__ __forceinline__ float roundtf(float x) { return __uint_as_float(f2tf(x)); }

__device__ __forceinline__ uint32_t s2u(const void* p) {
    uint32_t a;
    asm("{ .reg .u64 t; cvta.to.shared.u64 t, %1; cvt.u32.u64 %0, t; }" : "=r"(a) : "l"(p));
    return a;
}
__device__ __forceinline__ void cpa16(uint32_t d, const void* s) {
    asm volatile("cp.async.cg.shared.global [%0], [%1], 16;\n" :: "r"(d), "l"(s));
}
__device__ __forceinline__ void cpa16p(uint32_t d, const void* s, bool pred) {
    int sz = pred ? 16 : 0;
    asm volatile("cp.async.cg.shared.global [%0], [%1], 16, %2;\n" :: "r"(d), "l"(s), "r"(sz));
}
#define CP_COMMIT() asm volatile("cp.async.commit_group;\n")
#define CP_WAIT(N)  asm volatile("cp.async.wait_group %0;\n" :: "n"(N))

__device__ __forceinline__ void mma_tf32(float& c0, float& c1, float& c2, float& c3,
                                         unsigned a0, unsigned a1, unsigned a2, unsigned a3,
                                         unsigned b0, unsigned b1) {
    asm volatile(
        "mma.sync.aligned.m16n8k8.row.col.f32.tf32.tf32.f32 "
        "{%0,%1,%2,%3}, {%4,%5,%6,%7}, {%8,%9}, {%0,%1,%2,%3};\n"
        : "+f"(c0), "+f"(c1), "+f"(c2), "+f"(c3)
        : "r"(a0), "r"(a1), "r"(a2), "r"(a3), "r"(b0), "r"(b1));
}

// ---------------- tf32 pre-rounding of inputs --------------------------------
__global__ __launch_bounds__(256) void round5(const float4* __restrict__ h,
                                              const float4* __restrict__ wq,
                                              const float4* __restrict__ wkva,
                                              const float4* __restrict__ wkvb,
                                              const float4* __restrict__ wo) {
    const int n0 = T_TOK * HID / 4;
    const int n1 = HID * QDIM / 4;
    const int n2 = HID * KVADIM / 4;
    const int n3 = KVD * KVBDIM / 4;
    const int n4 = ODIM * HID / 4;
    const int total = n0 + n1 + n2 + n3 + n4;
    for (int i = blockIdx.x * 256 + threadIdx.x; i < total; i += gridDim.x * 256) {
        const float4* s;
        float4* d;
        int j = i;
        if (j < n0)              { s = h;    d = (float4*)g_hid;  }
        else if ((j -= n0) < n1) { s = wq;   d = (float4*)g_wq;   }
        else if ((j -= n1) < n2) { s = wkva; d = (float4*)g_wkva; }
        else if ((j -= n2) < n3) { s = wkvb; d = (float4*)g_wkvb; }
        else { j -= n3;            s = wo;   d = (float4*)g_wo;   }
        float4 v = s[j];
        v.x = roundtf(v.x); v.y = roundtf(v.y); v.z = roundtf(v.z); v.w = roundtf(v.w);
        d[j] = v;
    }
}

// ---------------- cp.async double-buffered tf32 GEMM -------------------------
#define AP 36
#define BP 136
#define GEMM_SMEM ((2 * 128 * AP + 2 * 32 * BP) * 4)

__global__ __launch_bounds__(256, 2) void gemm_cp(const float* __restrict__ A,
                                                  const float* __restrict__ B,
                                                  float* __restrict__ C,
                                                  int M, int N, int K, int round_out) {
    extern __shared__ float sm[];
    float* As = sm;                  // 2 stages of 128*AP
    float* Bs = sm + 2 * 128 * AP;   // 2 stages of 32*BP
    const uint32_t as_u = s2u(As);
    const uint32_t bs_u = s2u(Bs);

    const int tid = threadIdx.x;
    const int lane = tid & 31;
    const int wid = tid >> 5;
    const int g = lane >> 2;
    const int tg = lane & 3;
    const int wm = wid & 1;
    const int wn = wid >> 1;
    const int crow = blockIdx.y * 128;
    const int ccol = blockIdx.x * 128;

    const int am = tid >> 3;
    const int ak = (tid & 7) << 2;
    const int bk = tid >> 5;
    const int bn = (tid & 31) << 2;
    const bool bpred = (ccol + bn) < N;

    float acc[4][4][4];
#pragma unroll
    for (int mt = 0; mt < 4; mt++)
#pragma unroll
        for (int nt = 0; nt < 4; nt++)
#pragma unroll
            for (int c = 0; c < 4; c++) acc[mt][nt][c] = 0.f;

    const int nk = K >> 5;

    // issue tile 0
    {
        int k0 = 0;
#pragma unroll
        for (int i = 0; i < 4; i++)
            cpa16(as_u + (((am + 32 * i) * AP + ak) << 2),
                  A + (size_t)(crow + am + 32 * i) * K + k0 + ak);
#pragma unroll
        for (int i = 0; i < 4; i++)
            cpa16p(bs_u + (((bk + 8 * i) * BP + bn) << 2),
                   B + (size_t)(k0 + bk + 8 * i) * N + ccol + bn, bpred);
        CP_COMMIT();
    }

    for (int kt = 0; kt < nk; kt++) {
        CP_WAIT(0);
        __syncthreads();
        int buf = kt & 1;
        // prefetch next tile into other buffer (overlaps with compute below)
        if (kt + 1 < nk) {
            int nbuf = buf ^ 1;
            int k0 = (kt + 1) << 5;
            uint32_t au = as_u + nbuf * 128 * AP * 4;
            uint32_t bu = bs_u + nbuf * 32 * BP * 4;
#pragma unroll
            for (int i = 0; i < 4; i++)
                cpa16(au + (((am + 32 * i) * AP + ak) << 2),
                      A + (size_t)(crow + am + 32 * i) * K + k0 + ak);
#pragma unroll
            for (int i = 0; i < 4; i++)
                cpa16p(bu + (((bk + 8 * i) * BP + bn) << 2),
                       B + (size_t)(k0 + bk + 8 * i) * N + ccol + bn, bpred);
            CP_COMMIT();
        }
        const unsigned* Asu = (const unsigned*)(As + buf * 128 * AP);
        const unsigned* Bsu = (const unsigned*)(Bs + buf * 32 * BP);
#pragma unroll
        for (int ks = 0; ks < 4; ks++) {
            int k = ks << 3;
            unsigned af[4][4], bf[4][2];
#pragma unroll
            for (int mt = 0; mt < 4; mt++) {
                int m0 = wm * 64 + mt * 16;
                af[mt][0] = Asu[(m0 + g) * AP + k + tg];
                af[mt][1] = Asu[(m0 + 8 + g) * AP + k + tg];
                af[mt][2] = Asu[(m0 + g) * AP + k + tg + 4];
                af[mt][3] = Asu[(m0 + 8 + g) * AP + k + tg + 4];
            }
#pragma unroll
            for (int nt = 0; nt < 4; nt++) {
                int n0 = wn * 32 + nt * 8;
                bf[nt][0] = Bsu[(k + tg) * BP + n0 + g];
                bf[nt][1] = Bsu[(k + tg + 4) * BP + n0 + g];
            }
#pragma unroll
            for (int mt = 0; mt < 4; mt++)
#pragma unroll
                for (int nt = 0; nt < 4; nt++)
                    mma_tf32(acc[mt][nt][0], acc[mt][nt][1], acc[mt][nt][2], acc[mt][nt][3],
                             af[mt][0], af[mt][1], af[mt][2], af[mt][3],
                             bf[nt][0], bf[nt][1]);
        }
        __syncthreads();
    }

#pragma unroll
    for (int mt = 0; mt < 4; mt++) {
        int row = crow + wm * 64 + mt * 16 + g;
#pragma unroll
        for (int nt = 0; nt < 4; nt++) {
            int col = ccol + wn * 32 + nt * 8 + tg * 2;
            if (col < N) {
                float2 v0 = make_float2(acc[mt][nt][0], acc[mt][nt][1]);
                float2 v1 = make_float2(acc[mt][nt][2], acc[mt][nt][3]);
                if (round_out) {
                    v0.x = roundtf(v0.x); v0.y = roundtf(v0.y);
                    v1.x = roundtf(v1.x); v1.y = roundtf(v1.y);
                }
                *(float2*)(C + (size_t)row * N + col) = v0;
                *(float2*)(C + (size_t)(row + 8) * N + col) = v1;
            }
        }
    }
}

// ---------------- RMSNorm + RoPE (outputs tf32-rounded) ----------------------
__global__ __launch_bounds__(256) void norm_rope(const int* __restrict__ positions,
                                                 const float* __restrict__ lnw) {
    int t   = blockIdx.x;
    int tid = threadIdx.x;
    const float* kvrow = g_kv + (size_t)t * KVADIM;

    float ss = 0.f;
    for (int i = tid; i < KVD; i += 256) {
        float v = kvrow[i];
        ss += v * v;
    }
#pragma unroll
    for (int o = 16; o > 0; o >>= 1) ss += __shfl_xor_sync(0xFFFFFFFFu, ss, o);
    __shared__ float red[8];
    if ((tid & 31) == 0) red[tid >> 5] = ss;
    __syncthreads();
    float tot = 0.f;
#pragma unroll
    for (int w = 0; w < 8; w++) tot += red[w];
    float inv = rsqrtf(tot * (1.f / KVD) + 1e-6f);

    for (int i = tid; i < KVD; i += 256)
        g_kvc[(size_t)t * KVD + i] = roundtf(kvrow[i] * inv * lnw[i]);

    float pos = (float)positions[t];

    for (int i = tid; i < DR / 2; i += 256) {
        float invf = (float)exp(-((double)(2 * i) / (double)DR) * 9.210340371976184);
        float f = pos * invf;
        float c = cosf(f), s = sinf(f);
        float x1 = kvrow[KVD + 2 * i];
        float x2 = kvrow[KVD + 2 * i + 1];
        g_kpe[(size_t)t * DR + 2 * i]     = roundtf(x1 * c - x2 * s);
        g_kpe[(size_t)t * DR + 2 * i + 1] = roundtf(x2 * c + x1 * s);
    }

    for (int idx = tid; idx < NH * (DR / 2); idx += 256) {
        int h = idx / (DR / 2);
        int i = idx % (DR / 2);
        float invf = (float)exp(-((double)(2 * i) / (double)DR) * 9.210340371976184);
        float f = pos * invf;
        float c = cosf(f), s = sinf(f);
        float* qp = g_q + (size_t)t * QDIM + h * DQK + DN + 2 * i;
        float x1 = qp[0], x2 = qp[1];
        qp[0] = roundtf(x1 * c - x2 * s);
        qp[1] = roundtf(x2 * c + x1 * s);
    }
}

// ---------------- flash attention, tf32 mma, cp.async pipelined --------------
#define BQ 128
#define BKT 64
#define QP 196
#define VP 132
#define PP 68
#define ATT_SMEM ((BQ * QP + BKT * QP + BKT * VP + BQ * PP) * 4)

__global__ __launch_bounds__(256, 1) void attn_kernel() {
    extern __shared__ float sm[];
    float* Qs = sm;
    float* Ks = Qs + BQ * QP;
    float* Vs = Ks + BKT * QP;
    float* Ps = Vs + BKT * VP;
    const uint32_t qs_u = s2u(Qs);
    const uint32_t ks_u = s2u(Ks);
    const uint32_t vs_u = s2u(Vs);

    const int bid = blockIdx.x;
    const int qb = bid & 15;
    const int h  = bid >> 4;
    const int q0 = qb * BQ;
    const int tid = threadIdx.x;
    const int lane = tid & 31;
    const int wid = tid >> 5;
    const int g = lane >> 2;
    const int tg = lane & 3;
    const int m0 = wid * 16;

    const unsigned* Qsu = (const unsigned*)Qs;
    const unsigned* Ksu = (const unsigned*)Ks;
    const unsigned* Vsu = (const unsigned*)Vs;
    const unsigned* Psu = (const unsigned*)Ps;

    // issue Q loads (group), then K[0] (group)
#pragma unroll
    for (int i = 0; i < 24; i++) {
        int idx = tid + 256 * i;
        int r = idx / 48, c = idx % 48;
        cpa16(qs_u + ((r * QP + c * 4) << 2),
              g_q + (size_t)(q0 + r) * QDIM + h * DQK + c * 4);
    }
    CP_COMMIT();
    {
#pragma unroll
        for (int i = 0; i < 12; i++) {
            int idx = tid + 256 * i;
            int r = idx / 48, c = idx % 48;
            const float* src = (c < 32)
                ? (g_kvb + (size_t)r * KVBDIM + h * 256 + c * 4)
                : (g_kpe + (size_t)r * DR + (c - 32) * 4);
            cpa16(ks_u + ((r * QP + c * 4) << 2), src);
        }
        CP_COMMIT();
    }

    float m_i[2] = {-1e30f, -1e30f};
    float l_i[2] = {0.f, 0.f};
    float oacc[16][4];
#pragma unroll
    for (int nt = 0; nt < 16; nt++)
#pragma unroll
        for (int c = 0; c < 4; c++) oacc[nt][c] = 0.f;

    const int r0 = q0 + m0 + g;
    const int r1 = r0 + 8;
    const int nkb = qb * 2 + 2;

    for (int kb = 0; kb < nkb; kb++) {
        int k0 = kb * BKT;
        // issue V[kb] (Vs free: fresh or end-of-loop sync)
#pragma unroll
        for (int i = 0; i < 8; i++) {
            int idx = tid + 256 * i;
            int r = idx >> 5, c = idx & 31;
            cpa16(vs_u + ((r * VP + c * 4) << 2),
                  g_kvb + (size_t)(k0 + r) * KVBDIM + h * 256 + DN + c * 4);
        }
        CP_COMMIT();
        CP_WAIT(1);        // Q (first iter) and K[kb] complete; V may be in flight
        __syncthreads();

        // S = Q @ K^T
        float sacc[8][4];
#pragma unroll
        for (int nt = 0; nt < 8; nt++)
#pragma unroll
            for (int c = 0; c < 4; c++) sacc[nt][c] = 0.f;
#pragma unroll
        for (int ks = 0; ks < 24; ks++) {
            int k = ks * 8;
            unsigned a0 = Qsu[(m0 + g) * QP + k + tg];
            unsigned a1 = Qsu[(m0 + 8 + g) * QP + k + tg];
            unsigned a2 = Qsu[(m0 + g) * QP + k + tg + 4];
            unsigned a3 = Qsu[(m0 + 8 + g) * QP + k + tg + 4];
#pragma unroll
            for (int nt = 0; nt < 8; nt++) {
                unsigned b0 = Ksu[(nt * 8 + g) * QP + k + tg];
                unsigned b1 = Ksu[(nt * 8 + g) * QP + k + tg + 4];
                mma_tf32(sacc[nt][0], sacc[nt][1], sacc[nt][2], sacc[nt][3],
                         a0, a1, a2, a3, b0, b1);
            }
        }

        CP_WAIT(0);        // V[kb] ready
        __syncthreads();   // all warps done reading Ks

        // prefetch K[kb+1] (overwrites Ks; overlaps softmax+PV)
        if (kb + 1 < nkb) {
            int k1 = (kb + 1) * BKT;
#pragma unroll
            for (int i = 0; i < 12; i++) {
                int idx = tid + 256 * i;
                int r = idx / 48, c = idx % 48;
                const float* src = (c < 32)
                    ? (g_kvb + (size_t)(k1 + r) * KVBDIM + h * 256 + c * 4)
                    : (g_kpe + (size_t)(k1 + r) * DR + (c - 32) * 4);
                cpa16(ks_u + ((r * QP + c * 4) << 2), src);
            }
            CP_COMMIT();
        }

        // scale + causal mask
#pragma unroll
        for (int nt = 0; nt < 8; nt++) {
            int c0i = k0 + nt * 8 + tg * 2;
            sacc[nt][0] = (c0i     <= r0) ? sacc[nt][0] * ATT_SCALE : -1e30f;
            sacc[nt][1] = (c0i + 1 <= r0) ? sacc[nt][1] * ATT_SCALE : -1e30f;
            sacc[nt][2] = (c0i     <= r1) ? sacc[nt][2] * ATT_SCALE : -1e30f;
            sacc[nt][3] = (c0i + 1 <= r1) ? sacc[nt][3] * ATT_SCALE : -1e30f;
        }

        // online softmax
        float mx0 = -1e30f, mx1 = -1e30f;
#pragma unroll
        for (int nt = 0; nt < 8; nt++) {
            mx0 = fmaxf(mx0, fmaxf(sacc[nt][0], sacc[nt][1]));
            mx1 = fmaxf(mx1, fmaxf(sacc[nt][2], sacc[nt][3]));
        }
        mx0 = fmaxf(mx0, __shfl_xor_sync(0xFFFFFFFFu, mx0, 1));
        mx0 = fmaxf(mx0, __shfl_xor_sync(0xFFFFFFFFu, mx0, 2));
        mx1 = fmaxf(mx1, __shfl_xor_sync(0xFFFFFFFFu, mx1, 1));
        mx1 = fmaxf(mx1, __shfl_xor_sync(0xFFFFFFFFu, mx1, 2));

        float nm0 = fmaxf(m_i[0], mx0);
        float nm1 = fmaxf(m_i[1], mx1);
        float al0 = __expf(m_i[0] - nm0);
        float al1 = __expf(m_i[1] - nm1);
        m_i[0] = nm0; m_i[1] = nm1;

        float rs0 = 0.f, rs1 = 0.f;
#pragma unroll
        for (int nt = 0; nt < 8; nt++) {
            float p0 = __expf(sacc[nt][0] - nm0);
            float p1 = __expf(sacc[nt][1] - nm0);
            float p2 = __expf(sacc[nt][2] - nm1);
            float p3 = __expf(sacc[nt][3] - nm1);
            sacc[nt][0] = p0; sacc[nt][1] = p1; sacc[nt][2] = p2; sacc[nt][3] = p3;
            rs0 += p0 + p1; rs1 += p2 + p3;
        }
        rs0 += __shfl_xor_sync(0xFFFFFFFFu, rs0, 1);
        rs0 += __shfl_xor_sync(0xFFFFFFFFu, rs0, 2);
        rs1 += __shfl_xor_sync(0xFFFFFFFFu, rs1, 1);
        rs1 += __shfl_xor_sync(0xFFFFFFFFu, rs1, 2);
        l_i[0] = l_i[0] * al0 + rs0;
        l_i[1] = l_i[1] * al1 + rs1;

#pragma unroll
        for (int nt = 0; nt < 16; nt++) {
            oacc[nt][0] *= al0; oacc[nt][1] *= al0;
            oacc[nt][2] *= al1; oacc[nt][3] *= al1;
        }

        // store P (warp-private)
#pragma unroll
        for (int nt = 0; nt < 8; nt++) {
            int col = nt * 8 + tg * 2;
            *(uint2*)&Ps[(m0 + g) * PP + col] =
                make_uint2(f2tf(sacc[nt][0]), f2tf(sacc[nt][1]));
            *(uint2*)&Ps[(m0 + 8 + g) * PP + col] =
                make_uint2(f2tf(sacc[nt][2]), f2tf(sacc[nt][3]));
        }
        __syncwarp();

        // O += P @ V
#pragma unroll
        for (int ks = 0; ks < 8; ks++) {
            int k = ks * 8;
            unsigned a0 = Psu[(m0 + g) * PP + k + tg];
            unsigned a1 = Psu[(m0 + 8 + g) * PP + k + tg];
            unsigned a2 = Psu[(m0 + g) * PP + k + tg + 4];
            unsigned a3 = Psu[(m0 + 8 + g) * PP + k + tg + 4];
#pragma unroll
            for (int nt = 0; nt < 16; nt++) {
                unsigned b0 = Vsu[(k + tg) * VP + nt * 8 + g];
                unsigned b1 = Vsu[(k + tg + 4) * VP + nt * 8 + g];
                mma_tf32(oacc[nt][0], oacc[nt][1], oacc[nt][2], oacc[nt][3],
                         a0, a1, a2, a3, b0, b1);
            }
        }
        __syncthreads();   // all done reading Vs before next V issue
    }

    float inv0 = 1.f / l_i[0];
    float inv1 = 1.f / l_i[1];
#pragma unroll
    for (int nt = 0; nt < 16; nt++) {
        int col = nt * 8 + tg * 2;
        *(float2*)&g_attn[(size_t)r0 * ODIM + h * DV + col] =
            make_float2(roundtf(oacc[nt][0] * inv0), roundtf(oacc[nt][1] * inv0));
        *(float2*)&g_attn[(size_t)r1 * ODIM + h * DV + col] =
            make_float2(roundtf(oacc[nt][2] * inv1), roundtf(oacc[nt][3] * inv1));
    }
}

// ---------------- launch ----------------------------------------------------
extern "C" void kernel_launch(void* const* d_in, const int* in_sizes, int n_in,
                              void* d_out, int out_size) {
    const int*   positions = (const int*)d_in[0];
    const float* hidden    = (const float*)d_in[1];
    const float* w_q       = (const float*)d_in[2];
    const float* w_kv_a    = (const float*)d_in[3];
    const float* kv_a_ln_w = (const float*)d_in[4];
    const float* w_kv_b    = (const float*)d_in[5];
    const float* w_o       = (const float*)d_in[6];
    float* out = (float*)d_out;

    float *p_q, *p_kv, *p_kvc, *p_kvb, *p_attn;
    float *p_hid, *p_wq, *p_wkva, *p_wkvb, *p_wo;
    cudaGetSymbolAddress((void**)&p_q,    g_q);
    cudaGetSymbolAddress((void**)&p_kv,   g_kv);
    cudaGetSymbolAddress((void**)&p_kvc,  g_kvc);
    cudaGetSymbolAddress((void**)&p_kvb,  g_kvb);
    cudaGetSymbolAddress((void**)&p_attn, g_attn);
    cudaGetSymbolAddress((void**)&p_hid,  g_hid);
    cudaGetSymbolAddress((void**)&p_wq,   g_wq);
    cudaGetSymbolAddress((void**)&p_wkva, g_wkva);
    cudaGetSymbolAddress((void**)&p_wkvb, g_wkvb);
    cudaGetSymbolAddress((void**)&p_wo,   g_wo);

    cudaFuncSetAttribute(gemm_cp, cudaFuncAttributeMaxDynamicSharedMemorySize, GEMM_SMEM);
    cudaFuncSetAttribute(attn_kernel, cudaFuncAttributeMaxDynamicSharedMemorySize, ATT_SMEM);

    // 0. pre-round inputs to tf32
    round5<<<2048, 256>>>((const float4*)hidden, (const float4*)w_q,
                          (const float4*)w_kv_a, (const float4*)w_kv_b,
                          (const float4*)w_o);
    // 1. q = hid @ w_q (rounded out)
    gemm_cp<<<dim3(QDIM / 128, T_TOK / 128), 256, GEMM_SMEM>>>(p_hid, p_wq, p_q, T_TOK, QDIM, HID, 1);
    // 2. kv = hid @ w_kv_a (fp32 out)
    gemm_cp<<<dim3((KVADIM + 127) / 128, T_TOK / 128), 256, GEMM_SMEM>>>(p_hid, p_wkva, p_kv, T_TOK, KVADIM, HID, 0);
    // 3. rmsnorm + rope (rounded outs)
    norm_rope<<<T_TOK, 256>>>(positions, kv_a_ln_w);
    // 4. kvb = kv_c @ w_kv_b (rounded out)
    gemm_cp<<<dim3(KVBDIM / 128, T_TOK / 128), 256, GEMM_SMEM>>>(p_kvc, p_wkvb, p_kvb, T_TOK, KVBDIM, KVD, 1);
    // 5. attention (rounded out)
    attn_kernel<<<T_TOK / BQ * NH, 256, ATT_SMEM>>>();
    // 6. out = attn @ w_o (fp32 out)
    gemm_cp<<<dim3(HID / 128, T_TOK / 128), 256, GEMM_SMEM>>>(p_attn, p_wo, out, T_TOK, HID, ODIM, 0);
}

// round 6
// speedup vs baseline: 11.4922x; 2.1552x over previous
#include <cuda_runtime.h>
#include <cuda_fp16.h>
#include <cstdint>
#include <math.h>

// Problem constants
#define T_TOK 2048
#define HID   2048
#define NH    16
#define DN    128
#define DR    64
#define DV    128
#define KVD   512
#define DQK   192
#define QDIM  (NH*DQK)      // 3072
#define KVADIM (KVD + DR)   // 576
#define KVBDIM (NH*(DN+DV)) // 4096
#define ODIM  (NH*DV)       // 2048
#define ATT_SCALE 0.07216878364870323f

// ---------------- scratch ----------------------------------------------------
__device__ __half g_hidh[(size_t)T_TOK * HID];
__device__ __half g_wqT [(size_t)QDIM * HID];     // [N][K]
__device__ __half g_wkvaT[(size_t)KVADIM * HID];
__device__ __half g_wkvbT[(size_t)KVBDIM * KVD];
__device__ __half g_woT [(size_t)HID * ODIM];
__device__ __half g_qh  [(size_t)T_TOK * QDIM];
__device__ float  g_kv  [(size_t)T_TOK * KVADIM];
__device__ __half g_kvch[(size_t)T_TOK * KVD];
__device__ __half g_kpeh[(size_t)T_TOK * DR];
__device__ __half g_kvbh[(size_t)T_TOK * KVBDIM];
__device__ __half g_attnh[(size_t)T_TOK * ODIM];

// ---------------- helpers ----------------------------------------------------
__device__ __forceinline__ uint32_t s2u(const void* p) {
    uint32_t a;
    asm("{ .reg .u64 t; cvta.to.shared.u64 t, %1; cvt.u32.u64 %0, t; }" : "=r"(a) : "l"(p));
    return a;
}
__device__ __forceinline__ void cpa16(uint32_t d, const void* s) {
    asm volatile("cp.async.cg.shared.global [%0], [%1], 16;\n" :: "r"(d), "l"(s));
}
__device__ __forceinline__ void cpa16p(uint32_t d, const void* s, bool pred) {
    int sz = pred ? 16 : 0;
    asm volatile("cp.async.cg.shared.global [%0], [%1], 16, %2;\n" :: "r"(d), "l"(s), "r"(sz));
}
#define CP_COMMIT() asm volatile("cp.async.commit_group;\n")
#define CP_WAIT(N)  asm volatile("cp.async.wait_group %0;\n" :: "n"(N))

__device__ __forceinline__ void ldsm_x4(uint32_t* r, uint32_t a) {
    asm volatile("ldmatrix.sync.aligned.m8n8.x4.shared.b16 {%0,%1,%2,%3}, [%4];"
        : "=r"(r[0]), "=r"(r[1]), "=r"(r[2]), "=r"(r[3]) : "r"(a));
}
__device__ __forceinline__ void ldsm_x4t(uint32_t* r, uint32_t a) {
    asm volatile("ldmatrix.sync.aligned.m8n8.x4.trans.shared.b16 {%0,%1,%2,%3}, [%4];"
        : "=r"(r[0]), "=r"(r[1]), "=r"(r[2]), "=r"(r[3]) : "r"(a));
}
__device__ __forceinline__ void mma_h(float* c, const uint32_t* a, uint32_t b0, uint32_t b1) {
    asm volatile(
        "mma.sync.aligned.m16n8k16.row.col.f32.f16.f16.f32 "
        "{%0,%1,%2,%3}, {%4,%5,%6,%7}, {%8,%9}, {%0,%1,%2,%3};\n"
        : "+f"(c[0]), "+f"(c[1]), "+f"(c[2]), "+f"(c[3])
        : "r"(a[0]), "r"(a[1]), "r"(a[2]), "r"(a[3]), "r"(b0), "r"(b1));
}
__device__ __forceinline__ uint32_t packh2(float x, float y) {
    __half2 h = __floats2half2_rn(x, y);
    return *(uint32_t*)&h;
}

// ---------------- prepass: hidden fp32->fp16 ---------------------------------
__global__ __launch_bounds__(256) void convh(const float4* __restrict__ src) {
    const int n = T_TOK * HID / 4;
    uint2* dst = (uint2*)g_hidh;
    for (int i = blockIdx.x * 256 + threadIdx.x; i < n; i += gridDim.x * 256) {
        float4 v = src[i];
        dst[i] = make_uint2(packh2(v.x, v.y), packh2(v.z, v.w));
    }
}

// ---------------- prepass: weight transpose fp32 [K][N] -> fp16 [N][K] -------
__global__ __launch_bounds__(256) void transw(const float* __restrict__ src,
                                              __half* __restrict__ dst,
                                              int K, int N) {
    __shared__ float t[32][33];
    int n0 = blockIdx.x * 32, k0 = blockIdx.y * 32;
    int tx = threadIdx.x, ty = threadIdx.y;   // 32 x 8
#pragma unroll
    for (int j = 0; j < 32; j += 8)
        t[ty + j][tx] = src[(size_t)(k0 + ty + j) * N + n0 + tx];
    __syncthreads();
#pragma unroll
    for (int j = 0; j < 32; j += 8)
        dst[(size_t)(n0 + ty + j) * K + k0 + tx] = __float2half_rn(t[tx][ty + j]);
}

// ---------------- fp16 tensor-core GEMM: C[M,N] = A[M,K] @ Bt[N,K]^T ---------
// 128x128 tile, BK=32 halves, 3-stage cp.async, ldmatrix fragments.
#define PH 40                      // smem pitch in halves (phase-conflict-free)
#define STG (128 * PH)             // halves per matrix per stage
#define GEMM_SMEM (3 * 2 * STG * 2)

__global__ __launch_bounds__(256, 2) void gemm_h(const __half* __restrict__ A,
                                                 const __half* __restrict__ Bt,
                                                 float* __restrict__ Cf,
                                                 __half* __restrict__ Ch,
                                                 int M, int N, int K) {
    extern __shared__ __half smh[];
    __half* As = smh;
    __half* Bs = smh + 3 * STG;
    const uint32_t as_u = s2u(As);
    const uint32_t bs_u = s2u(Bs);

    const int tid = threadIdx.x;
    const int lane = tid & 31;
    const int wid = tid >> 5;
    const int g = lane >> 2;
    const int tg = lane & 3;
    const int wm = wid & 1;
    const int wn = wid >> 1;
    const int crow = blockIdx.y * 128;
    const int ccol = blockIdx.x * 128;

    const int lrow = tid >> 2;          // 0..63
    const int lcol = (tid & 3) << 3;    // 0,8,16,24 halves
    const int nk = K >> 5;

    float acc[4][4][4];
#pragma unroll
    for (int mt = 0; mt < 4; mt++)
#pragma unroll
        for (int nt = 0; nt < 4; nt++)
#pragma unroll
            for (int c = 0; c < 4; c++) acc[mt][nt][c] = 0.f;

    auto issue = [&](int kt) {
        int buf = kt % 3;
        int k0 = kt << 5;
        uint32_t au = as_u + (uint32_t)buf * STG * 2;
        uint32_t bu = bs_u + (uint32_t)buf * STG * 2;
#pragma unroll
        for (int i = 0; i < 2; i++) {
            int r = lrow + 64 * i;
            cpa16(au + ((r * PH + lcol) << 1),
                  A + (size_t)(crow + r) * K + k0 + lcol);
            cpa16p(bu + ((r * PH + lcol) << 1),
                   Bt + (size_t)(ccol + r) * K + k0 + lcol, (ccol + r) < N);
        }
    };

    issue(0); CP_COMMIT();
    issue(1); CP_COMMIT();

    const int arow = lane & 15;
    const int acol = (lane >> 4) << 3;
    const int brow = (lane & 7) + ((lane >> 4) << 3);
    const int bcol = ((lane >> 3) & 1) << 3;

    for (int kt = 0; kt < nk; kt++) {
        CP_WAIT(1);
        __syncthreads();
        if (kt + 2 < nk) issue(kt + 2);
        CP_COMMIT();

        int buf = kt % 3;
        uint32_t ab = as_u + (uint32_t)buf * STG * 2;
        uint32_t bb = bs_u + (uint32_t)buf * STG * 2;
#pragma unroll
        for (int ks = 0; ks < 2; ks++) {
            int k = ks << 4;
            uint32_t af[4][4], bf[2][4];
#pragma unroll
            for (int mt = 0; mt < 4; mt++)
                ldsm_x4(af[mt], ab + (((wm * 64 + mt * 16 + arow) * PH + k + acol) << 1));
#pragma unroll
            for (int np = 0; np < 2; np++)
                ldsm_x4(bf[np], bb + (((wn * 32 + np * 16 + brow) * PH + k + bcol) << 1));
#pragma unroll
            for (int mt = 0; mt < 4; mt++)
#pragma unroll
                for (int nt = 0; nt < 4; nt++)
                    mma_h(acc[mt][nt], af[mt],
                          bf[nt >> 1][(nt & 1) * 2], bf[nt >> 1][(nt & 1) * 2 + 1]);
        }
    }

#pragma unroll
    for (int mt = 0; mt < 4; mt++) {
        int row = crow + wm * 64 + mt * 16 + g;
#pragma unroll
        for (int nt = 0; nt < 4; nt++) {
            int col = ccol + wn * 32 + nt * 8 + tg * 2;
            if (col < N) {
                if (Ch) {
                    *(uint32_t*)&Ch[(size_t)row * N + col] =
                        packh2(acc[mt][nt][0], acc[mt][nt][1]);
                    *(uint32_t*)&Ch[(size_t)(row + 8) * N + col] =
                        packh2(acc[mt][nt][2], acc[mt][nt][3]);
                } else {
                    *(float2*)&Cf[(size_t)row * N + col] =
                        make_float2(acc[mt][nt][0], acc[mt][nt][1]);
                    *(float2*)&Cf[(size_t)(row + 8) * N + col] =
                        make_float2(acc[mt][nt][2], acc[mt][nt][3]);
                }
            }
        }
    }
}

// ---------------- RMSNorm + RoPE (fp32 in, fp16 out) -------------------------
__global__ __launch_bounds__(256) void norm_rope(const int* __restrict__ positions,
                                                 const float* __restrict__ lnw) {
    int t   = blockIdx.x;
    int tid = threadIdx.x;
    const float* kvrow = g_kv + (size_t)t * KVADIM;

    float ss = 0.f;
    for (int i = tid; i < KVD; i += 256) {
        float v = kvrow[i];
        ss += v * v;
    }
#pragma unroll
    for (int o = 16; o > 0; o >>= 1) ss += __shfl_xor_sync(0xFFFFFFFFu, ss, o);
    __shared__ float red[8];
    if ((tid & 31) == 0) red[tid >> 5] = ss;
    __syncthreads();
    float tot = 0.f;
#pragma unroll
    for (int w = 0; w < 8; w++) tot += red[w];
    float inv = rsqrtf(tot * (1.f / KVD) + 1e-6f);

    for (int i = tid; i < KVD; i += 256)
        g_kvch[(size_t)t * KVD + i] = __float2half_rn(kvrow[i] * inv * lnw[i]);

    float pos = (float)positions[t];

    for (int i = tid; i < DR / 2; i += 256) {
        float invf = (float)exp(-((double)(2 * i) / (double)DR) * 9.210340371976184);
        float f = pos * invf;
        float c = cosf(f), s = sinf(f);
        float x1 = kvrow[KVD + 2 * i];
        float x2 = kvrow[KVD + 2 * i + 1];
        *(uint32_t*)&g_kpeh[(size_t)t * DR + 2 * i] =
            packh2(x1 * c - x2 * s, x2 * c + x1 * s);
    }

    for (int idx = tid; idx < NH * (DR / 2); idx += 256) {
        int h = idx / (DR / 2);
        int i = idx % (DR / 2);
        float invf = (float)exp(-((double)(2 * i) / (double)DR) * 9.210340371976184);
        float f = pos * invf;
        float c = cosf(f), s = sinf(f);
        uint32_t* qp = (uint32_t*)&g_qh[(size_t)t * QDIM + h * DQK + DN + 2 * i];
        __half2 hv = *(__half2*)qp;
        float x1 = __low2float(hv), x2 = __high2float(hv);
        *qp = packh2(x1 * c - x2 * s, x2 * c + x1 * s);
    }
}

// ---------------- flash attention, fp16 mma, cp.async pipelined --------------
#define BQ 128
#define BKT 64
#define QPH 200    // Q/K pitch in halves (400B rows; phase-conflict-free)
#define VPH 136    // V pitch (272B rows)
#define ATT_SMEM ((BQ * QPH + BKT * QPH + BKT * VPH) * 2)

__global__ __launch_bounds__(256) void attn_h() {
    extern __shared__ __half smh[];
    __half* Qs = smh;
    __half* Ks = Qs + BQ * QPH;
    __half* Vs = Ks + BKT * QPH;
    const uint32_t qs_u = s2u(Qs);
    const uint32_t ks_u = s2u(Ks);
    const uint32_t vs_u = s2u(Vs);

    const int bid = blockIdx.x;
    const int qb = 15 - (bid >> 4);   // heavy q-blocks first
    const int h  = bid & 15;
    const int q0 = qb * BQ;
    const int tid = threadIdx.x;
    const int lane = tid & 31;
    const int wid = tid >> 5;
    const int g = lane >> 2;
    const int tg = lane & 3;
    const int m0 = wid * 16;

    // Q tile (12 chunks/thread)
#pragma unroll
    for (int i = 0; i < 12; i++) {
        int c = tid + 256 * i;
        int r = c / 24, cc = c % 24;
        cpa16(qs_u + ((r * QPH + cc * 8) << 1),
              g_qh + (size_t)(q0 + r) * QDIM + h * DQK + cc * 8);
    }
    CP_COMMIT();

    auto issueK = [&](int t0) {
#pragma unroll
        for (int i = 0; i < 6; i++) {
            int c = tid + 256 * i;
            int r = c / 24, cc = c % 24;
            const __half* src = (cc < 16)
                ? g_kvbh + (size_t)(t0 + r) * KVBDIM + h * 256 + cc * 8
                : g_kpeh + (size_t)(t0 + r) * DR + (cc - 16) * 8;
            cpa16(ks_u + ((r * QPH + cc * 8) << 1), src);
        }
    };
    auto issueV = [&](int t0) {
#pragma unroll
        for (int i = 0; i < 4; i++) {
            int c = tid + 256 * i;
            int r = c >> 4, cc = c & 15;
            cpa16(vs_u + ((r * VPH + cc * 8) << 1),
                  g_kvbh + (size_t)(t0 + r) * KVBDIM + h * 256 + DN + cc * 8);
        }
    };

    issueK(0); CP_COMMIT();

    float m_i[2] = {-1e30f, -1e30f};
    float l_i[2] = {0.f, 0.f};
    float oacc[16][4];
#pragma unroll
    for (int nt = 0; nt < 16; nt++)
#pragma unroll
        for (int c = 0; c < 4; c++) oacc[nt][c] = 0.f;

    const int r0 = q0 + m0 + g;
    const int r1 = r0 + 8;
    const int nkb = qb * 2 + 2;

    const int arow = lane & 15;
    const int acol = (lane >> 4) << 3;
    const int brow = (lane & 7) + ((lane >> 4) << 3);
    const int bcol = ((lane >> 3) & 1) << 3;
    const int vrow = (lane & 7) + (((lane >> 3) & 1) << 3);
    const int vcol = (lane >> 4) << 3;

    for (int kb = 0; kb < nkb; kb++) {
        int k0 = kb * BKT;
        issueV(k0); CP_COMMIT();
        CP_WAIT(1);          // Q(+K first iter) / K[kb] complete
        __syncthreads();

        // S = Q @ K^T
        float sacc[8][4];
#pragma unroll
        for (int nt = 0; nt < 8; nt++)
#pragma unroll
            for (int c = 0; c < 4; c++) sacc[nt][c] = 0.f;
#pragma unroll
        for (int kc = 0; kc < 12; kc++) {
            int k = kc * 16;
            uint32_t af[4], bf[4][4];
            ldsm_x4(af, qs_u + (((m0 + arow) * QPH + k + acol) << 1));
#pragma unroll
            for (int np = 0; np < 4; np++)
                ldsm_x4(bf[np], ks_u + (((np * 16 + brow) * QPH + k + bcol) << 1));
#pragma unroll
            for (int nt = 0; nt < 8; nt++)
                mma_h(sacc[nt], af, bf[nt >> 1][(nt & 1) * 2], bf[nt >> 1][(nt & 1) * 2 + 1]);
        }

        CP_WAIT(0);          // V[kb] ready
        __syncthreads();     // all warps done reading Ks
        if (kb + 1 < nkb) issueK(k0 + BKT);
        CP_COMMIT();

        // scale + causal mask
#pragma unroll
        for (int nt = 0; nt < 8; nt++) {
            int c0i = k0 + nt * 8 + tg * 2;
            sacc[nt][0] = (c0i     <= r0) ? sacc[nt][0] * ATT_SCALE : -1e30f;
            sacc[nt][1] = (c0i + 1 <= r0) ? sacc[nt][1] * ATT_SCALE : -1e30f;
            sacc[nt][2] = (c0i     <= r1) ? sacc[nt][2] * ATT_SCALE : -1e30f;
            sacc[nt][3] = (c0i + 1 <= r1) ? sacc[nt][3] * ATT_SCALE : -1e30f;
        }

        // online softmax (quad reduction)
        float mx0 = -1e30f, mx1 = -1e30f;
#pragma unroll
        for (int nt = 0; nt < 8; nt++) {
            mx0 = fmaxf(mx0, fmaxf(sacc[nt][0], sacc[nt][1]));
            mx1 = fmaxf(mx1, fmaxf(sacc[nt][2], sacc[nt][3]));
        }
        mx0 = fmaxf(mx0, __shfl_xor_sync(0xFFFFFFFFu, mx0, 1));
        mx0 = fmaxf(mx0, __shfl_xor_sync(0xFFFFFFFFu, mx0, 2));
        mx1 = fmaxf(mx1, __shfl_xor_sync(0xFFFFFFFFu, mx1, 1));
        mx1 = fmaxf(mx1, __shfl_xor_sync(0xFFFFFFFFu, mx1, 2));

        float nm0 = fmaxf(m_i[0], mx0);
        float nm1 = fmaxf(m_i[1], mx1);
        float al0 = __expf(m_i[0] - nm0);
        float al1 = __expf(m_i[1] - nm1);
        m_i[0] = nm0; m_i[1] = nm1;

        float rs0 = 0.f, rs1 = 0.f;
#pragma unroll
        for (int nt = 0; nt < 8; nt++) {
            float p0 = __expf(sacc[nt][0] - nm0);
            float p1 = __expf(sacc[nt][1] - nm0);
            float p2 = __expf(sacc[nt][2] - nm1);
            float p3 = __expf(sacc[nt][3] - nm1);
            sacc[nt][0] = p0; sacc[nt][1] = p1; sacc[nt][2] = p2; sacc[nt][3] = p3;
            rs0 += p0 + p1; rs1 += p2 + p3;
        }
        rs0 += __shfl_xor_sync(0xFFFFFFFFu, rs0, 1);
        rs0 += __shfl_xor_sync(0xFFFFFFFFu, rs0, 2);
        rs1 += __shfl_xor_sync(0xFFFFFFFFu, rs1, 1);
        rs1 += __shfl_xor_sync(0xFFFFFFFFu, rs1, 2);
        l_i[0] = l_i[0] * al0 + rs0;
        l_i[1] = l_i[1] * al1 + rs1;

#pragma unroll
        for (int nt = 0; nt < 16; nt++) {
            oacc[nt][0] *= al0; oacc[nt][1] *= al0;
            oacc[nt][2] *= al1; oacc[nt][3] *= al1;
        }

        // O += P @ V  (P direct from registers: C-frag == A-frag layout)
#pragma unroll
        for (int kc = 0; kc < 4; kc++) {
            uint32_t pa[4];
            pa[0] = packh2(sacc[2 * kc][0],     sacc[2 * kc][1]);
            pa[1] = packh2(sacc[2 * kc][2],     sacc[2 * kc][3]);
            pa[2] = packh2(sacc[2 * kc + 1][0], sacc[2 * kc + 1][1]);
            pa[3] = packh2(sacc[2 * kc + 1][2], sacc[2 * kc + 1][3]);
            int k = kc * 16;
#pragma unroll
            for (int np = 0; np < 8; np++) {
                uint32_t vf[4];
                ldsm_x4t(vf, vs_u + (((k + vrow) * VPH + np * 16 + vcol) << 1));
                mma_h(oacc[np * 2],     pa, vf[0], vf[1]);
                mma_h(oacc[np * 2 + 1], pa, vf[2], vf[3]);
            }
        }
        __syncthreads();     // done with Vs before next V issue
    }

    float inv0 = 1.f / l_i[0];
    float inv1 = 1.f / l_i[1];
#pragma unroll
    for (int nt = 0; nt < 16; nt++) {
        int col = h * DV + nt * 8 + tg * 2;
        *(uint32_t*)&g_attnh[(size_t)r0 * ODIM + col] =
            packh2(oacc[nt][0] * inv0, oacc[nt][1] * inv0);
        *(uint32_t*)&g_attnh[(size_t)r1 * ODIM + col] =
            packh2(oacc[nt][2] * inv1, oacc[nt][3] * inv1);
    }
}

// ---------------- launch ----------------------------------------------------
extern "C" void kernel_launch(void* const* d_in, const int* in_sizes, int n_in,
                              void* d_out, int out_size) {
    const int*   positions = (const int*)d_in[0];
    const float* hidden    = (const float*)d_in[1];
    const float* w_q       = (const float*)d_in[2];
    const float* w_kv_a    = (const float*)d_in[3];
    const float* kv_a_ln_w = (const float*)d_in[4];
    const float* w_kv_b    = (const float*)d_in[5];
    const float* w_o       = (const float*)d_in[6];
    float* out = (float*)d_out;

    __half *p_hidh, *p_wqT, *p_wkvaT, *p_wkvbT, *p_woT;
    __half *p_qh, *p_kvch, *p_kvbh, *p_attnh;
    float *p_kv;
    cudaGetSymbolAddress((void**)&p_hidh,  g_hidh);
    cudaGetSymbolAddress((void**)&p_wqT,   g_wqT);
    cudaGetSymbolAddress((void**)&p_wkvaT, g_wkvaT);
    cudaGetSymbolAddress((void**)&p_wkvbT, g_wkvbT);
    cudaGetSymbolAddress((void**)&p_woT,   g_woT);
    cudaGetSymbolAddress((void**)&p_qh,    g_qh);
    cudaGetSymbolAddress((void**)&p_kvch,  g_kvch);
    cudaGetSymbolAddress((void**)&p_kvbh,  g_kvbh);
    cudaGetSymbolAddress((void**)&p_attnh, g_attnh);
    cudaGetSymbolAddress((void**)&p_kv,    g_kv);

    cudaFuncSetAttribute(gemm_h, cudaFuncAttributeMaxDynamicSharedMemorySize, GEMM_SMEM);
    cudaFuncSetAttribute(attn_h, cudaFuncAttributeMaxDynamicSharedMemorySize, ATT_SMEM);

    // 0. prepass: convert + transpose
    convh<<<1024, 256>>>((const float4*)hidden);
    transw<<<dim3(QDIM / 32, HID / 32), dim3(32, 8)>>>(w_q, p_wqT, HID, QDIM);
    transw<<<dim3(KVADIM / 32, HID / 32), dim3(32, 8)>>>(w_kv_a, p_wkvaT, HID, KVADIM);
    transw<<<dim3(KVBDIM / 32, KVD / 32), dim3(32, 8)>>>(w_kv_b, p_wkvbT, KVD, KVBDIM);
    transw<<<dim3(HID / 32, ODIM / 32), dim3(32, 8)>>>(w_o, p_woT, ODIM, HID);

    // 1. q = hid @ w_q (fp16 out)
    gemm_h<<<dim3(QDIM / 128, T_TOK / 128), 256, GEMM_SMEM>>>(
        p_hidh, p_wqT, nullptr, p_qh, T_TOK, QDIM, HID);
    // 2. kv = hid @ w_kv_a (fp32 out)
    gemm_h<<<dim3((KVADIM + 127) / 128, T_TOK / 128), 256, GEMM_SMEM>>>(
        p_hidh, p_wkvaT, p_kv, nullptr, T_TOK, KVADIM, HID);
    // 3. rmsnorm + rope
    norm_rope<<<T_TOK, 256>>>(positions, kv_a_ln_w);
    // 4. kvb = kv_c @ w_kv_b (fp16 out)
    gemm_h<<<dim3(KVBDIM / 128, T_TOK / 128), 256, GEMM_SMEM>>>(
        p_kvch, p_wkvbT, nullptr, p_kvbh, T_TOK, KVBDIM, KVD);
    // 5. attention
    attn_h<<<T_TOK / BQ * NH, 256, ATT_SMEM>>>();
    // 6. out = attn @ w_o (fp32 out)
    gemm_h<<<dim3(HID / 128, T_TOK / 128), 256, GEMM_SMEM>>>(
        p_attnh, p_woT, out, nullptr, T_TOK, HID, ODIM);
}

// round 7
// speedup vs baseline: 11.8194x; 1.0285x over previous
#include <cuda_runtime.h>
#include <cuda_fp16.h>
#include <cstdint>
#include <math.h>

// Problem constants
#define T_TOK 2048
#define HID   2048
#define NH    16
#define DN    128
#define DR    64
#define DV    128
#define KVD   512
#define DQK   192
#define QDIM  (NH*DQK)      // 3072
#define KVADIM (KVD + DR)   // 576
#define QKVDIM (QDIM + KVADIM) // 3648
#define KVBDIM (NH*(DN+DV)) // 4096
#define ODIM  (NH*DV)       // 2048
#define ATT_SCALE 0.07216878364870323f

// ---------------- scratch ----------------------------------------------------
__device__ __half g_hidh[(size_t)T_TOK * HID];
__device__ __half g_wqkvT[(size_t)QKVDIM * HID];   // [N][K]: rows 0..3071 = wq, 3072.. = wkva
__device__ __half g_wkvbT[(size_t)KVBDIM * KVD];
__device__ __half g_woT [(size_t)HID * ODIM];
__device__ __half g_qkvh[(size_t)T_TOK * QKVDIM];  // q (roped in place) | kv raw
__device__ __half g_kvch[(size_t)T_TOK * KVD];
__device__ __half g_kpeh[(size_t)T_TOK * DR];
__device__ __half g_kvbh[(size_t)T_TOK * KVBDIM];
__device__ __half g_attnh[(size_t)T_TOK * ODIM];

// ---------------- helpers ----------------------------------------------------
__device__ __forceinline__ uint32_t s2u(const void* p) {
    uint32_t a;
    asm("{ .reg .u64 t; cvta.to.shared.u64 t, %1; cvt.u32.u64 %0, t; }" : "=r"(a) : "l"(p));
    return a;
}
__device__ __forceinline__ void cpa16(uint32_t d, const void* s) {
    asm volatile("cp.async.cg.shared.global [%0], [%1], 16;\n" :: "r"(d), "l"(s));
}
__device__ __forceinline__ void cpa16p(uint32_t d, const void* s, bool pred) {
    int sz = pred ? 16 : 0;
    asm volatile("cp.async.cg.shared.global [%0], [%1], 16, %2;\n" :: "r"(d), "l"(s), "r"(sz));
}
#define CP_COMMIT() asm volatile("cp.async.commit_group;\n")
#define CP_WAIT(N)  asm volatile("cp.async.wait_group %0;\n" :: "n"(N))

__device__ __forceinline__ void ldsm_x4(uint32_t* r, uint32_t a) {
    asm volatile("ldmatrix.sync.aligned.m8n8.x4.shared.b16 {%0,%1,%2,%3}, [%4];"
        : "=r"(r[0]), "=r"(r[1]), "=r"(r[2]), "=r"(r[3]) : "r"(a));
}
__device__ __forceinline__ void ldsm_x4t(uint32_t* r, uint32_t a) {
    asm volatile("ldmatrix.sync.aligned.m8n8.x4.trans.shared.b16 {%0,%1,%2,%3}, [%4];"
        : "=r"(r[0]), "=r"(r[1]), "=r"(r[2]), "=r"(r[3]) : "r"(a));
}
__device__ __forceinline__ void mma_h(float* c, const uint32_t* a, uint32_t b0, uint32_t b1) {
    asm volatile(
        "mma.sync.aligned.m16n8k16.row.col.f32.f16.f16.f32 "
        "{%0,%1,%2,%3}, {%4,%5,%6,%7}, {%8,%9}, {%0,%1,%2,%3};\n"
        : "+f"(c[0]), "+f"(c[1]), "+f"(c[2]), "+f"(c[3])
        : "r"(a[0]), "r"(a[1]), "r"(a[2]), "r"(a[3]), "r"(b0), "r"(b1));
}
__device__ __forceinline__ uint32_t packh2(float x, float y) {
    __half2 h = __floats2half2_rn(x, y);
    return *(uint32_t*)&h;
}

// ---------------- prepass: hidden fp32->fp16 ---------------------------------
__global__ __launch_bounds__(256) void convh(const float4* __restrict__ src) {
    const int n = T_TOK * HID / 4;
    uint2* dst = (uint2*)g_hidh;
    for (int i = blockIdx.x * 256 + threadIdx.x; i < n; i += gridDim.x * 256) {
        float4 v = src[i];
        dst[i] = make_uint2(packh2(v.x, v.y), packh2(v.z, v.w));
    }
}

// ---------------- prepass: batched weight transpose fp32[K][N]->fp16[N][K] ---
__global__ __launch_bounds__(256) void transw_all(const float* __restrict__ wq,
                                                  const float* __restrict__ wkva,
                                                  const float* __restrict__ wkvb,
                                                  const float* __restrict__ wo) {
    const float* src;
    __half* dst;
    int K, N;
    switch (blockIdx.z) {
        case 0: src = wq;   dst = g_wqkvT;               K = HID; N = QDIM;   break;
        case 1: src = wkva; dst = g_wqkvT + (size_t)QDIM * HID; K = HID; N = KVADIM; break;
        case 2: src = wkvb; dst = g_wkvbT;               K = KVD; N = KVBDIM; break;
        default: src = wo;  dst = g_woT;                 K = ODIM; N = HID;   break;
    }
    int n0 = blockIdx.x * 32, k0 = blockIdx.y * 32;
    if (n0 >= N || k0 >= K) return;
    __shared__ float t[32][33];
    int tx = threadIdx.x & 31, ty = (threadIdx.x >> 5) * 4;  // remap 256 -> 32x8
    int tyy = threadIdx.x >> 5;
#pragma unroll
    for (int j = 0; j < 32; j += 8)
        t[tyy + j][tx] = src[(size_t)(k0 + tyy + j) * N + n0 + tx];
    __syncthreads();
#pragma unroll
    for (int j = 0; j < 32; j += 8)
        dst[(size_t)(n0 + tyy + j) * K + k0 + tx] = __float2half_rn(t[tx][tyy + j]);
    (void)ty;
}

// ---------------- fp16 tensor-core GEMM: C[M,N] = A[M,K] @ Bt[N,K]^T ---------
#define PH 40
#define STG (128 * PH)
#define GEMM_SMEM (3 * 2 * STG * 2)

__global__ __launch_bounds__(256, 2) void gemm_h(const __half* __restrict__ A,
                                                 const __half* __restrict__ Bt,
                                                 float* __restrict__ Cf,
                                                 __half* __restrict__ Ch,
                                                 int M, int N, int K) {
    extern __shared__ __half smh[];
    __half* As = smh;
    __half* Bs = smh + 3 * STG;
    const uint32_t as_u = s2u(As);
    const uint32_t bs_u = s2u(Bs);

    const int tid = threadIdx.x;
    const int lane = tid & 31;
    const int wid = tid >> 5;
    const int g = lane >> 2;
    const int tg = lane & 3;
    const int wm = wid & 1;
    const int wn = wid >> 1;
    const int crow = blockIdx.y * 128;
    const int ccol = blockIdx.x * 128;

    const int lrow = tid >> 2;
    const int lcol = (tid & 3) << 3;
    const int nk = K >> 5;

    float acc[4][4][4];
#pragma unroll
    for (int mt = 0; mt < 4; mt++)
#pragma unroll
        for (int nt = 0; nt < 4; nt++)
#pragma unroll
            for (int c = 0; c < 4; c++) acc[mt][nt][c] = 0.f;

    auto issue = [&](int kt) {
        int buf = kt % 3;
        int k0 = kt << 5;
        uint32_t au = as_u + (uint32_t)buf * STG * 2;
        uint32_t bu = bs_u + (uint32_t)buf * STG * 2;
#pragma unroll
        for (int i = 0; i < 2; i++) {
            int r = lrow + 64 * i;
            cpa16(au + ((r * PH + lcol) << 1),
                  A + (size_t)(crow + r) * K + k0 + lcol);
            cpa16p(bu + ((r * PH + lcol) << 1),
                   Bt + (size_t)(ccol + r) * K + k0 + lcol, (ccol + r) < N);
        }
    };

    issue(0); CP_COMMIT();
    issue(1); CP_COMMIT();

    const int arow = lane & 15;
    const int acol = (lane >> 4) << 3;
    const int brow = (lane & 7) + ((lane >> 4) << 3);
    const int bcol = ((lane >> 3) & 1) << 3;

    for (int kt = 0; kt < nk; kt++) {
        CP_WAIT(1);
        __syncthreads();
        if (kt + 2 < nk) issue(kt + 2);
        CP_COMMIT();

        int buf = kt % 3;
        uint32_t ab = as_u + (uint32_t)buf * STG * 2;
        uint32_t bb = bs_u + (uint32_t)buf * STG * 2;
#pragma unroll
        for (int ks = 0; ks < 2; ks++) {
            int k = ks << 4;
            uint32_t af[4][4], bf[2][4];
#pragma unroll
            for (int mt = 0; mt < 4; mt++)
                ldsm_x4(af[mt], ab + (((wm * 64 + mt * 16 + arow) * PH + k + acol) << 1));
#pragma unroll
            for (int np = 0; np < 2; np++)
                ldsm_x4(bf[np], bb + (((wn * 32 + np * 16 + brow) * PH + k + bcol) << 1));
#pragma unroll
            for (int mt = 0; mt < 4; mt++)
#pragma unroll
                for (int nt = 0; nt < 4; nt++)
                    mma_h(acc[mt][nt], af[mt],
                          bf[nt >> 1][(nt & 1) * 2], bf[nt >> 1][(nt & 1) * 2 + 1]);
        }
    }

#pragma unroll
    for (int mt = 0; mt < 4; mt++) {
        int row = crow + wm * 64 + mt * 16 + g;
#pragma unroll
        for (int nt = 0; nt < 4; nt++) {
            int col = ccol + wn * 32 + nt * 8 + tg * 2;
            if (col < N) {
                if (Ch) {
                    *(uint32_t*)&Ch[(size_t)row * N + col] =
                        packh2(acc[mt][nt][0], acc[mt][nt][1]);
                    *(uint32_t*)&Ch[(size_t)(row + 8) * N + col] =
                        packh2(acc[mt][nt][2], acc[mt][nt][3]);
                } else {
                    *(float2*)&Cf[(size_t)row * N + col] =
                        make_float2(acc[mt][nt][0], acc[mt][nt][1]);
                    *(float2*)&Cf[(size_t)(row + 8) * N + col] =
                        make_float2(acc[mt][nt][2], acc[mt][nt][3]);
                }
            }
        }
    }
}

// ---------------- RMSNorm + RoPE (fp16 in, fp16 out) -------------------------
__global__ __launch_bounds__(256) void norm_rope(const int* __restrict__ positions,
                                                 const float* __restrict__ lnw) {
    int t   = blockIdx.x;
    int tid = threadIdx.x;
    const __half* kvrow = g_qkvh + (size_t)t * QKVDIM + QDIM;

    float ss = 0.f;
    for (int i = tid; i < KVD; i += 256) {
        float v = __half2float(kvrow[i]);
        ss += v * v;
    }
#pragma unroll
    for (int o = 16; o > 0; o >>= 1) ss += __shfl_xor_sync(0xFFFFFFFFu, ss, o);
    __shared__ float red[8];
    if ((tid & 31) == 0) red[tid >> 5] = ss;
    __syncthreads();
    float tot = 0.f;
#pragma unroll
    for (int w = 0; w < 8; w++) tot += red[w];
    float inv = rsqrtf(tot * (1.f / KVD) + 1e-6f);

    for (int i = tid; i < KVD; i += 256)
        g_kvch[(size_t)t * KVD + i] = __float2half_rn(__half2float(kvrow[i]) * inv * lnw[i]);

    float pos = (float)positions[t];

    for (int i = tid; i < DR / 2; i += 256) {
        float invf = (float)exp(-((double)(2 * i) / (double)DR) * 9.210340371976184);
        float f = pos * invf;
        float c = cosf(f), s = sinf(f);
        __half2 hv = *(__half2*)&kvrow[KVD + 2 * i];
        float x1 = __low2float(hv), x2 = __high2float(hv);
        *(uint32_t*)&g_kpeh[(size_t)t * DR + 2 * i] =
            packh2(x1 * c - x2 * s, x2 * c + x1 * s);
    }

    for (int idx = tid; idx < NH * (DR / 2); idx += 256) {
        int h = idx / (DR / 2);
        int i = idx % (DR / 2);
        float invf = (float)exp(-((double)(2 * i) / (double)DR) * 9.210340371976184);
        float f = pos * invf;
        float c = cosf(f), s = sinf(f);
        uint32_t* qp = (uint32_t*)&g_qkvh[(size_t)t * QKVDIM + h * DQK + DN + 2 * i];
        __half2 hv = *(__half2*)qp;
        float x1 = __low2float(hv), x2 = __high2float(hv);
        *qp = packh2(x1 * c - x2 * s, x2 * c + x1 * s);
    }
}

// ---------------- flash attention, fp16 mma, cp.async pipelined --------------
#define BQ 128
#define BKT 64
#define QPH 200
#define VPH 136
#define ATT_SMEM ((BQ * QPH + BKT * QPH + BKT * VPH) * 2)

__global__ __launch_bounds__(256) void attn_h() {
    extern __shared__ __half smh[];
    __half* Qs = smh;
    __half* Ks = Qs + BQ * QPH;
    __half* Vs = Ks + BKT * QPH;
    const uint32_t qs_u = s2u(Qs);
    const uint32_t ks_u = s2u(Ks);
    const uint32_t vs_u = s2u(Vs);

    const int bid = blockIdx.x;
    const int qb = 15 - (bid >> 4);
    const int h  = bid & 15;
    const int q0 = qb * BQ;
    const int tid = threadIdx.x;
    const int lane = tid & 31;
    const int wid = tid >> 5;
    const int g = lane >> 2;
    const int tg = lane & 3;
    const int m0 = wid * 16;

#pragma unroll
    for (int i = 0; i < 12; i++) {
        int c = tid + 256 * i;
        int r = c / 24, cc = c % 24;
        cpa16(qs_u + ((r * QPH + cc * 8) << 1),
              g_qkvh + (size_t)(q0 + r) * QKVDIM + h * DQK + cc * 8);
    }
    CP_COMMIT();

    auto issueK = [&](int t0) {
#pragma unroll
        for (int i = 0; i < 6; i++) {
            int c = tid + 256 * i;
            int r = c / 24, cc = c % 24;
            const __half* src = (cc < 16)
                ? g_kvbh + (size_t)(t0 + r) * KVBDIM + h * 256 + cc * 8
                : g_kpeh + (size_t)(t0 + r) * DR + (cc - 16) * 8;
            cpa16(ks_u + ((r * QPH + cc * 8) << 1), src);
        }
    };
    auto issueV = [&](int t0) {
#pragma unroll
        for (int i = 0; i < 4; i++) {
            int c = tid + 256 * i;
            int r = c >> 4, cc = c & 15;
            cpa16(vs_u + ((r * VPH + cc * 8) << 1),
                  g_kvbh + (size_t)(t0 + r) * KVBDIM + h * 256 + DN + cc * 8);
        }
    };

    issueK(0); CP_COMMIT();

    float m_i[2] = {-1e30f, -1e30f};
    float l_i[2] = {0.f, 0.f};
    float oacc[16][4];
#pragma unroll
    for (int nt = 0; nt < 16; nt++)
#pragma unroll
        for (int c = 0; c < 4; c++) oacc[nt][c] = 0.f;

    const int r0 = q0 + m0 + g;
    const int r1 = r0 + 8;
    const int nkb = qb * 2 + 2;

    const int arow = lane & 15;
    const int acol = (lane >> 4) << 3;
    const int brow = (lane & 7) + ((lane >> 4) << 3);
    const int bcol = ((lane >> 3) & 1) << 3;
    const int vrow = (lane & 7) + (((lane >> 3) & 1) << 3);
    const int vcol = (lane >> 4) << 3;

    for (int kb = 0; kb < nkb; kb++) {
        int k0 = kb * BKT;
        issueV(k0); CP_COMMIT();
        CP_WAIT(1);
        __syncthreads();

        float sacc[8][4];
#pragma unroll
        for (int nt = 0; nt < 8; nt++)
#pragma unroll
            for (int c = 0; c < 4; c++) sacc[nt][c] = 0.f;
#pragma unroll
        for (int kc = 0; kc < 12; kc++) {
            int k = kc * 16;
            uint32_t af[4], bf[4][4];
            ldsm_x4(af, qs_u + (((m0 + arow) * QPH + k + acol) << 1));
#pragma unroll
            for (int np = 0; np < 4; np++)
                ldsm_x4(bf[np], ks_u + (((np * 16 + brow) * QPH + k + bcol) << 1));
#pragma unroll
            for (int nt = 0; nt < 8; nt++)
                mma_h(sacc[nt], af, bf[nt >> 1][(nt & 1) * 2], bf[nt >> 1][(nt & 1) * 2 + 1]);
        }

        CP_WAIT(0);
        __syncthreads();
        if (kb + 1 < nkb) issueK(k0 + BKT);
        CP_COMMIT();

#pragma unroll
        for (int nt = 0; nt < 8; nt++) {
            int c0i = k0 + nt * 8 + tg * 2;
            sacc[nt][0] = (c0i     <= r0) ? sacc[nt][0] * ATT_SCALE : -1e30f;
            sacc[nt][1] = (c0i + 1 <= r0) ? sacc[nt][1] * ATT_SCALE : -1e30f;
            sacc[nt][2] = (c0i     <= r1) ? sacc[nt][2] * ATT_SCALE : -1e30f;
            sacc[nt][3] = (c0i + 1 <= r1) ? sacc[nt][3] * ATT_SCALE : -1e30f;
        }

        float mx0 = -1e30f, mx1 = -1e30f;
#pragma unroll
        for (int nt = 0; nt < 8; nt++) {
            mx0 = fmaxf(mx0, fmaxf(sacc[nt][0], sacc[nt][1]));
            mx1 = fmaxf(mx1, fmaxf(sacc[nt][2], sacc[nt][3]));
        }
        mx0 = fmaxf(mx0, __shfl_xor_sync(0xFFFFFFFFu, mx0, 1));
        mx0 = fmaxf(mx0, __shfl_xor_sync(0xFFFFFFFFu, mx0, 2));
        mx1 = fmaxf(mx1, __shfl_xor_sync(0xFFFFFFFFu, mx1, 1));
        mx1 = fmaxf(mx1, __shfl_xor_sync(0xFFFFFFFFu, mx1, 2));

        float nm0 = fmaxf(m_i[0], mx0);
        float nm1 = fmaxf(m_i[1], mx1);
        float al0 = __expf(m_i[0] - nm0);
        float al1 = __expf(m_i[1] - nm1);
        m_i[0] = nm0; m_i[1] = nm1;

        float rs0 = 0.f, rs1 = 0.f;
#pragma unroll
        for (int nt = 0; nt < 8; nt++) {
            float p0 = __expf(sacc[nt][0] - nm0);
            float p1 = __expf(sacc[nt][1] - nm0);
            float p2 = __expf(sacc[nt][2] - nm1);
            float p3 = __expf(sacc[nt][3] - nm1);
            sacc[nt][0] = p0; sacc[nt][1] = p1; sacc[nt][2] = p2; sacc[nt][3] = p3;
            rs0 += p0 + p1; rs1 += p2 + p3;
        }
        rs0 += __shfl_xor_sync(0xFFFFFFFFu, rs0, 1);
        rs0 += __shfl_xor_sync(0xFFFFFFFFu, rs0, 2);
        rs1 += __shfl_xor_sync(0xFFFFFFFFu, rs1, 1);
        rs1 += __shfl_xor_sync(0xFFFFFFFFu, rs1, 2);
        l_i[0] = l_i[0] * al0 + rs0;
        l_i[1] = l_i[1] * al1 + rs1;

#pragma unroll
        for (int nt = 0; nt < 16; nt++) {
            oacc[nt][0] *= al0; oacc[nt][1] *= al0;
            oacc[nt][2] *= al1; oacc[nt][3] *= al1;
        }

#pragma unroll
        for (int kc = 0; kc < 4; kc++) {
            uint32_t pa[4];
            pa[0] = packh2(sacc[2 * kc][0],     sacc[2 * kc][1]);
            pa[1] = packh2(sacc[2 * kc][2],     sacc[2 * kc][3]);
            pa[2] = packh2(sacc[2 * kc + 1][0], sacc[2 * kc + 1][1]);
            pa[3] = packh2(sacc[2 * kc + 1][2], sacc[2 * kc + 1][3]);
            int k = kc * 16;
#pragma unroll
            for (int np = 0; np < 8; np++) {
                uint32_t vf[4];
                ldsm_x4t(vf, vs_u + (((k + vrow) * VPH + np * 16 + vcol) << 1));
                mma_h(oacc[np * 2],     pa, vf[0], vf[1]);
                mma_h(oacc[np * 2 + 1], pa, vf[2], vf[3]);
            }
        }
        __syncthreads();
    }

    float inv0 = 1.f / l_i[0];
    float inv1 = 1.f / l_i[1];
#pragma unroll
    for (int nt = 0; nt < 16; nt++) {
        int col = h * DV + nt * 8 + tg * 2;
        *(uint32_t*)&g_attnh[(size_t)r0 * ODIM + col] =
            packh2(oacc[nt][0] * inv0, oacc[nt][1] * inv0);
        *(uint32_t*)&g_attnh[(size_t)r1 * ODIM + col] =
            packh2(oacc[nt][2] * inv1, oacc[nt][3] * inv1);
    }
}

// ---------------- launch ----------------------------------------------------
extern "C" void kernel_launch(void* const* d_in, const int* in_sizes, int n_in,
                              void* d_out, int out_size) {
    const int*   positions = (const int*)d_in[0];
    const float* hidden    = (const float*)d_in[1];
    const float* w_q       = (const float*)d_in[2];
    const float* w_kv_a    = (const float*)d_in[3];
    const float* kv_a_ln_w = (const float*)d_in[4];
    const float* w_kv_b    = (const float*)d_in[5];
    const float* w_o       = (const float*)d_in[6];
    float* out = (float*)d_out;

    __half *p_hidh, *p_wqkvT, *p_wkvbT, *p_woT;
    __half *p_qkvh, *p_kvch, *p_kvbh, *p_attnh;
    cudaGetSymbolAddress((void**)&p_hidh,  g_hidh);
    cudaGetSymbolAddress((void**)&p_wqkvT, g_wqkvT);
    cudaGetSymbolAddress((void**)&p_wkvbT, g_wkvbT);
    cudaGetSymbolAddress((void**)&p_woT,   g_woT);
    cudaGetSymbolAddress((void**)&p_qkvh,  g_qkvh);
    cudaGetSymbolAddress((void**)&p_kvch,  g_kvch);
    cudaGetSymbolAddress((void**)&p_kvbh,  g_kvbh);
    cudaGetSymbolAddress((void**)&p_attnh, g_attnh);

    cudaFuncSetAttribute(gemm_h, cudaFuncAttributeMaxDynamicSharedMemorySize, GEMM_SMEM);
    cudaFuncSetAttribute(attn_h, cudaFuncAttributeMaxDynamicSharedMemorySize, ATT_SMEM);

    // 0. prepass: convert hidden + transpose all 4 weights (one launch each)
    convh<<<1024, 256>>>((const float4*)hidden);
    transw_all<<<dim3(KVBDIM / 32, HID / 32, 4), 256>>>(w_q, w_kv_a, w_kv_b, w_o);

    // 1. [q | kv] = hid @ [w_q | w_kv_a]   (fp16 out, N=3648)
    gemm_h<<<dim3((QKVDIM + 127) / 128, T_TOK / 128), 256, GEMM_SMEM>>>(
        p_hidh, p_wqkvT, nullptr, p_qkvh, T_TOK, QKVDIM, HID);
    // 2. rmsnorm + rope
    norm_rope<<<T_TOK, 256>>>(positions, kv_a_ln_w);
    // 3. kvb = kv_c @ w_kv_b (fp16 out)
    gemm_h<<<dim3(KVBDIM / 128, T_TOK / 128), 256, GEMM_SMEM>>>(
        p_kvch, p_wkvbT, nullptr, p_kvbh, T_TOK, KVBDIM, KVD);
    // 4. attention
    attn_h<<<T_TOK / BQ * NH, 256, ATT_SMEM>>>();
    // 5. out = attn @ w_o (fp32 out)
    gemm_h<<<dim3(HID / 128, T_TOK / 128), 256, GEMM_SMEM>>>(
        p_attnh, p_woT, out, nullptr, T_TOK, HID, ODIM);
}

// round 9
// speedup vs baseline: 12.9972x; 1.0997x over previous
#include <cuda_runtime.h>
#include <cuda_fp16.h>
#include <cstdint>
#include <math.h>

// Problem constants
#define T_TOK 2048
#define HID   2048
#define NH    16
#define DN    128
#define DR    64
#define DV    128
#define KVD   512
#define DQK   192
#define QDIM  (NH*DQK)      // 3072
#define KVADIM (KVD + DR)   // 576
#define QKVDIM (QDIM + KVADIM) // 3648
#define KVBDIM (NH*(DN+DV)) // 4096
#define ODIM  (NH*DV)       // 2048
#define ATT_SCALE 0.07216878364870323f

// ---------------- scratch ----------------------------------------------------
__device__ __half g_hidh[(size_t)T_TOK * HID];
__device__ __half g_wqkvT[(size_t)QKVDIM * HID];   // [N][K]
__device__ __half g_wkvbT[(size_t)KVBDIM * KVD];
__device__ __half g_woT [(size_t)HID * ODIM];
__device__ __half g_qkvh[(size_t)T_TOK * QKVDIM];
__device__ __half g_kvch[(size_t)T_TOK * KVD];
__device__ __half g_kpeh[(size_t)T_TOK * DR];
__device__ __half g_kvbh[(size_t)T_TOK * KVBDIM];
__device__ __half g_attnh[(size_t)T_TOK * ODIM];

// ---------------- helpers ----------------------------------------------------
__device__ __forceinline__ uint32_t s2u(const void* p) {
    uint32_t a;
    asm("{ .reg .u64 t; cvta.to.shared.u64 t, %1; cvt.u32.u64 %0, t; }" : "=r"(a) : "l"(p));
    return a;
}
__device__ __forceinline__ void cpa16(uint32_t d, const void* s) {
    asm volatile("cp.async.cg.shared.global [%0], [%1], 16;\n" :: "r"(d), "l"(s));
}
__device__ __forceinline__ void cpa16p(uint32_t d, const void* s, bool pred) {
    int sz = pred ? 16 : 0;
    asm volatile("cp.async.cg.shared.global [%0], [%1], 16, %2;\n" :: "r"(d), "l"(s), "r"(sz));
}
#define CP_COMMIT() asm volatile("cp.async.commit_group;\n")
#define CP_WAIT(N)  asm volatile("cp.async.wait_group %0;\n" :: "n"(N))

__device__ __forceinline__ void ldsm_x4(uint32_t* r, uint32_t a) {
    asm volatile("ldmatrix.sync.aligned.m8n8.x4.shared.b16 {%0,%1,%2,%3}, [%4];"
        : "=r"(r[0]), "=r"(r[1]), "=r"(r[2]), "=r"(r[3]) : "r"(a));
}
__device__ __forceinline__ void ldsm_x4t(uint32_t* r, uint32_t a) {
    asm volatile("ldmatrix.sync.aligned.m8n8.x4.trans.shared.b16 {%0,%1,%2,%3}, [%4];"
        : "=r"(r[0]), "=r"(r[1]), "=r"(r[2]), "=r"(r[3]) : "r"(a));
}
__device__ __forceinline__ void mma_h(float* c, const uint32_t* a, uint32_t b0, uint32_t b1) {
    asm volatile(
        "mma.sync.aligned.m16n8k16.row.col.f32.f16.f16.f32 "
        "{%0,%1,%2,%3}, {%4,%5,%6,%7}, {%8,%9}, {%0,%1,%2,%3};\n"
        : "+f"(c[0]), "+f"(c[1]), "+f"(c[2]), "+f"(c[3])
        : "r"(a[0]), "r"(a[1]), "r"(a[2]), "r"(a[3]), "r"(b0), "r"(b1));
}
__device__ __forceinline__ uint32_t packh2(float x, float y) {
    __half2 h = __floats2half2_rn(x, y);
    return *(uint32_t*)&h;
}

// ---------------- prepass: hidden fp32->fp16 ---------------------------------
__global__ __launch_bounds__(256) void convh(const float4* __restrict__ src) {
    const int n = T_TOK * HID / 4;
    uint2* dst = (uint2*)g_hidh;
    for (int i = blockIdx.x * 256 + threadIdx.x; i < n; i += gridDim.x * 256) {
        float4 v = src[i];
        dst[i] = make_uint2(packh2(v.x, v.y), packh2(v.z, v.w));
    }
}

// ---------------- prepass: batched weight transpose --------------------------
__global__ __launch_bounds__(256) void transw_all(const float* __restrict__ wq,
                                                  const float* __restrict__ wkva,
                                                  const float* __restrict__ wkvb,
                                                  const float* __restrict__ wo) {
    const float* src;
    __half* dst;
    int K, N;
    switch (blockIdx.z) {
        case 0: src = wq;   dst = g_wqkvT;               K = HID; N = QDIM;   break;
        case 1: src = wkva; dst = g_wqkvT + (size_t)QDIM * HID; K = HID; N = KVADIM; break;
        case 2: src = wkvb; dst = g_wkvbT;               K = KVD; N = KVBDIM; break;
        default: src = wo;  dst = g_woT;                 K = ODIM; N = HID;   break;
    }
    int n0 = blockIdx.x * 32, k0 = blockIdx.y * 32;
    if (n0 >= N || k0 >= K) return;
    __shared__ float t[32][33];
    int tx = threadIdx.x & 31;
    int tyy = threadIdx.x >> 5;
#pragma unroll
    for (int j = 0; j < 32; j += 8)
        t[tyy + j][tx] = src[(size_t)(k0 + tyy + j) * N + n0 + tx];
    __syncthreads();
#pragma unroll
    for (int j = 0; j < 32; j += 8)
        dst[(size_t)(n0 + tyy + j) * K + k0 + tx] = __float2half_rn(t[tx][tyy + j]);
}

// ---------------- fp16 GEMM: C[M,N] = A[M,K] @ Bt[N,K]^T ---------------------
// 128x128 CTA tile, 4 warps in 2x2 grid (64x64 warp tiles), BK=32, 3-stage
// cp.async. 128 threads, 2 CTAs/SM. LDS traffic: 8 ldsm.x4 per warp per k16
// for 32 mmas (128B/mma vs 192B/mma with 64x32 tiles).
#define PH 40
#define STG (128 * PH)
#define GEMM_SMEM (3 * 2 * STG * 2)

__global__ __launch_bounds__(128, 2) void gemm_h(const __half* __restrict__ A,
                                                 const __half* __restrict__ Bt,
                                                 float* __restrict__ Cf,
                                                 __half* __restrict__ Ch,
                                                 int M, int N, int K) {
    extern __shared__ __half smh[];
    __half* As = smh;
    __half* Bs = smh + 3 * STG;
    const uint32_t as_u = s2u(As);
    const uint32_t bs_u = s2u(Bs);

    const int tid = threadIdx.x;
    const int lane = tid & 31;
    const int wid = tid >> 5;
    const int g = lane >> 2;
    const int tg = lane & 3;
    const int wm = wid & 1;       // 0..1 -> m offset 0/64
    const int wn = wid >> 1;      // 0..1 -> n offset 0/64
    const int crow = blockIdx.y * 128;
    const int ccol = blockIdx.x * 128;

    const int lrow = tid >> 2;         // 0..31 (+32,+64,+96)
    const int lcol = (tid & 3) << 3;
    const int nk = K >> 5;

    float acc[4][8][4];
#pragma unroll
    for (int mt = 0; mt < 4; mt++)
#pragma unroll
        for (int nt = 0; nt < 8; nt++)
#pragma unroll
            for (int c = 0; c < 4; c++) acc[mt][nt][c] = 0.f;

    auto issue = [&](int kt) {
        int buf = kt % 3;
        int k0 = kt << 5;
        uint32_t au = as_u + (uint32_t)buf * STG * 2;
        uint32_t bu = bs_u + (uint32_t)buf * STG * 2;
#pragma unroll
        for (int i = 0; i < 4; i++) {
            int r = lrow + 32 * i;
            cpa16(au + ((r * PH + lcol) << 1),
                  A + (size_t)(crow + r) * K + k0 + lcol);
            cpa16p(bu + ((r * PH + lcol) << 1),
                   Bt + (size_t)(ccol + r) * K + k0 + lcol, (ccol + r) < N);
        }
    };

    issue(0); CP_COMMIT();
    issue(1); CP_COMMIT();

    const int arow = lane & 15;
    const int acol = (lane >> 4) << 3;
    const int brow = (lane & 7) + ((lane >> 4) << 3);
    const int bcol = ((lane >> 3) & 1) << 3;

    for (int kt = 0; kt < nk; kt++) {
        CP_WAIT(1);
        __syncthreads();
        if (kt + 2 < nk) issue(kt + 2);
        CP_COMMIT();

        int buf = kt % 3;
        uint32_t ab = as_u + (uint32_t)buf * STG * 2;
        uint32_t bb = bs_u + (uint32_t)buf * STG * 2;
#pragma unroll
        for (int ks = 0; ks < 2; ks++) {
            int k = ks << 4;
            uint32_t af[4][4], bf[4][4];
#pragma unroll
            for (int mt = 0; mt < 4; mt++)
                ldsm_x4(af[mt], ab + (((wm * 64 + mt * 16 + arow) * PH + k + acol) << 1));
#pragma unroll
            for (int np = 0; np < 4; np++)
                ldsm_x4(bf[np], bb + (((wn * 64 + np * 16 + brow) * PH + k + bcol) << 1));
#pragma unroll
            for (int mt = 0; mt < 4; mt++)
#pragma unroll
                for (int nt = 0; nt < 8; nt++)
                    mma_h(acc[mt][nt], af[mt],
                          bf[nt >> 1][(nt & 1) * 2], bf[nt >> 1][(nt & 1) * 2 + 1]);
        }
    }

#pragma unroll
    for (int mt = 0; mt < 4; mt++) {
        int row = crow + wm * 64 + mt * 16 + g;
#pragma unroll
        for (int nt = 0; nt < 8; nt++) {
            int col = ccol + wn * 64 + nt * 8 + tg * 2;
            if (col < N) {
                if (Ch) {
                    *(uint32_t*)&Ch[(size_t)row * N + col] =
                        packh2(acc[mt][nt][0], acc[mt][nt][1]);
                    *(uint32_t*)&Ch[(size_t)(row + 8) * N + col] =
                        packh2(acc[mt][nt][2], acc[mt][nt][3]);
                } else {
                    *(float2*)&Cf[(size_t)row * N + col] =
                        make_float2(acc[mt][nt][0], acc[mt][nt][1]);
                    *(float2*)&Cf[(size_t)(row + 8) * N + col] =
                        make_float2(acc[mt][nt][2], acc[mt][nt][3]);
                }
            }
        }
    }
}

// ---------------- RMSNorm + RoPE (fp16 in, fp16 out) -------------------------
__global__ __launch_bounds__(256) void norm_rope(const int* __restrict__ positions,
                                                 const float* __restrict__ lnw) {
    int t   = blockIdx.x;
    int tid = threadIdx.x;
    const __half* kvrow = g_qkvh + (size_t)t * QKVDIM + QDIM;

    float ss = 0.f;
    for (int i = tid; i < KVD; i += 256) {
        float v = __half2float(kvrow[i]);
        ss += v * v;
    }
#pragma unroll
    for (int o = 16; o > 0; o >>= 1) ss += __shfl_xor_sync(0xFFFFFFFFu, ss, o);
    __shared__ float red[8];
    if ((tid & 31) == 0) red[tid >> 5] = ss;
    __syncthreads();
    float tot = 0.f;
#pragma unroll
    for (int w = 0; w < 8; w++) tot += red[w];
    float inv = rsqrtf(tot * (1.f / KVD) + 1e-6f);

    for (int i = tid; i < KVD; i += 256)
        g_kvch[(size_t)t * KVD + i] = __float2half_rn(__half2float(kvrow[i]) * inv * lnw[i]);

    float pos = (float)positions[t];

    for (int i = tid; i < DR / 2; i += 256) {
        float invf = (float)exp(-((double)(2 * i) / (double)DR) * 9.210340371976184);
        float f = pos * invf;
        float c = cosf(f), s = sinf(f);
        __half2 hv = *(__half2*)&kvrow[KVD + 2 * i];
        float x1 = __low2float(hv), x2 = __high2float(hv);
        *(uint32_t*)&g_kpeh[(size_t)t * DR + 2 * i] =
            packh2(x1 * c - x2 * s, x2 * c + x1 * s);
    }

    for (int idx = tid; idx < NH * (DR / 2); idx += 256) {
        int h = idx / (DR / 2);
        int i = idx % (DR / 2);
        float invf = (float)exp(-((double)(2 * i) / (double)DR) * 9.210340371976184);
        float f = pos * invf;
        float c = cosf(f), s = sinf(f);
        uint32_t* qp = (uint32_t*)&g_qkvh[(size_t)t * QKVDIM + h * DQK + DN + 2 * i];
        __half2 hv = *(__half2*)qp;
        float x1 = __low2float(hv), x2 = __high2float(hv);
        *qp = packh2(x1 * c - x2 * s, x2 * c + x1 * s);
    }
}

// ---------------- flash attention, fp16 mma, cp.async pipelined --------------
#define BQ 128
#define BKT 64
#define QPH 200
#define VPH 136
#define ATT_SMEM ((BQ * QPH + BKT * QPH + BKT * VPH) * 2)

__global__ __launch_bounds__(256) void attn_h() {
    extern __shared__ __half smh2[];
    __half* Qs = smh2;
    __half* Ks = Qs + BQ * QPH;
    __half* Vs = Ks + BKT * QPH;
    const uint32_t qs_u = s2u(Qs);
    const uint32_t ks_u = s2u(Ks);
    const uint32_t vs_u = s2u(Vs);

    const int bid = blockIdx.x;
    const int qb = 15 - (bid >> 4);
    const int h  = bid & 15;
    const int q0 = qb * BQ;
    const int tid = threadIdx.x;
    const int lane = tid & 31;
    const int wid = tid >> 5;
    const int g = lane >> 2;
    const int tg = lane & 3;
    const int m0 = wid * 16;

#pragma unroll
    for (int i = 0; i < 12; i++) {
        int c = tid + 256 * i;
        int r = c / 24, cc = c % 24;
        cpa16(qs_u + ((r * QPH + cc * 8) << 1),
              g_qkvh + (size_t)(q0 + r) * QKVDIM + h * DQK + cc * 8);
    }
    CP_COMMIT();

    auto issueK = [&](int t0) {
#pragma unroll
        for (int i = 0; i < 6; i++) {
            int c = tid + 256 * i;
            int r = c / 24, cc = c % 24;
            const __half* src = (cc < 16)
                ? g_kvbh + (size_t)(t0 + r) * KVBDIM + h * 256 + cc * 8
                : g_kpeh + (size_t)(t0 + r) * DR + (cc - 16) * 8;
            cpa16(ks_u + ((r * QPH + cc * 8) << 1), src);
        }
    };
    auto issueV = [&](int t0) {
#pragma unroll
        for (int i = 0; i < 4; i++) {
            int c = tid + 256 * i;
            int r = c >> 4, cc = c & 15;
            cpa16(vs_u + ((r * VPH + cc * 8) << 1),
                  g_kvbh + (size_t)(t0 + r) * KVBDIM + h * 256 + DN + cc * 8);
        }
    };

    issueK(0); CP_COMMIT();

    float m_i[2] = {-1e30f, -1e30f};
    float l_i[2] = {0.f, 0.f};
    float oacc[16][4];
#pragma unroll
    for (int nt = 0; nt < 16; nt++)
#pragma unroll
        for (int c = 0; c < 4; c++) oacc[nt][c] = 0.f;

    const int r0 = q0 + m0 + g;
    const int r1 = r0 + 8;
    const int nkb = qb * 2 + 2;

    const int arow = lane & 15;
    const int acol = (lane >> 4) << 3;
    const int brow = (lane & 7) + ((lane >> 4) << 3);
    const int bcol = ((lane >> 3) & 1) << 3;
    const int vrow = (lane & 7) + (((lane >> 3) & 1) << 3);
    const int vcol = (lane >> 4) << 3;

    for (int kb = 0; kb < nkb; kb++) {
        int k0 = kb * BKT;
        issueV(k0); CP_COMMIT();
        CP_WAIT(1);
        __syncthreads();

        float sacc[8][4];
#pragma unroll
        for (int nt = 0; nt < 8; nt++)
#pragma unroll
            for (int c = 0; c < 4; c++) sacc[nt][c] = 0.f;
#pragma unroll
        for (int kc = 0; kc < 12; kc++) {
            int k = kc * 16;
            uint32_t af[4], bf[4][4];
            ldsm_x4(af, qs_u + (((m0 + arow) * QPH + k + acol) << 1));
#pragma unroll
            for (int np = 0; np < 4; np++)
                ldsm_x4(bf[np], ks_u + (((np * 16 + brow) * QPH + k + bcol) << 1));
#pragma unroll
            for (int nt = 0; nt < 8; nt++)
                mma_h(sacc[nt], af, bf[nt >> 1][(nt & 1) * 2], bf[nt >> 1][(nt & 1) * 2 + 1]);
        }

        CP_WAIT(0);
        __syncthreads();
        if (kb + 1 < nkb) issueK(k0 + BKT);
        CP_COMMIT();

#pragma unroll
        for (int nt = 0; nt < 8; nt++) {
            int c0i = k0 + nt * 8 + tg * 2;
            sacc[nt][0] = (c0i     <= r0) ? sacc[nt][0] * ATT_SCALE : -1e30f;
            sacc[nt][1] = (c0i + 1 <= r0) ? sacc[nt][1] * ATT_SCALE : -1e30f;
            sacc[nt][2] = (c0i     <= r1) ? sacc[nt][2] * ATT_SCALE : -1e30f;
            sacc[nt][3] = (c0i + 1 <= r1) ? sacc[nt][3] * ATT_SCALE : -1e30f;
        }

        float mx0 = -1e30f, mx1 = -1e30f;
#pragma unroll
        for (int nt = 0; nt < 8; nt++) {
            mx0 = fmaxf(mx0, fmaxf(sacc[nt][0], sacc[nt][1]));
            mx1 = fmaxf(mx1, fmaxf(sacc[nt][2], sacc[nt][3]));
        }
        mx0 = fmaxf(mx0, __shfl_xor_sync(0xFFFFFFFFu, mx0, 1));
        mx0 = fmaxf(mx0, __shfl_xor_sync(0xFFFFFFFFu, mx0, 2));
        mx1 = fmaxf(mx1, __shfl_xor_sync(0xFFFFFFFFu, mx1, 1));
        mx1 = fmaxf(mx1, __shfl_xor_sync(0xFFFFFFFFu, mx1, 2));

        float nm0 = fmaxf(m_i[0], mx0);
        float nm1 = fmaxf(m_i[1], mx1);
        float al0 = __expf(m_i[0] - nm0);
        float al1 = __expf(m_i[1] - nm1);
        m_i[0] = nm0; m_i[1] = nm1;

        float rs0 = 0.f, rs1 = 0.f;
#pragma unroll
        for (int nt = 0; nt < 8; nt++) {
            float p0 = __expf(sacc[nt][0] - nm0);
            float p1 = __expf(sacc[nt][1] - nm0);
            float p2 = __expf(sacc[nt][2] - nm1);
            float p3 = __expf(sacc[nt][3] - nm1);
            sacc[nt][0] = p0; sacc[nt][1] = p1; sacc[nt][2] = p2; sacc[nt][3] = p3;
            rs0 += p0 + p1; rs1 += p2 + p3;
        }
        rs0 += __shfl_xor_sync(0xFFFFFFFFu, rs0, 1);
        rs0 += __shfl_xor_sync(0xFFFFFFFFu, rs0, 2);
        rs1 += __shfl_xor_sync(0xFFFFFFFFu, rs1, 1);
        rs1 += __shfl_xor_sync(0xFFFFFFFFu, rs1, 2);
        l_i[0] = l_i[0] * al0 + rs0;
        l_i[1] = l_i[1] * al1 + rs1;

#pragma unroll
        for (int nt = 0; nt < 16; nt++) {
            oacc[nt][0] *= al0; oacc[nt][1] *= al0;
            oacc[nt][2] *= al1; oacc[nt][3] *= al1;
        }

#pragma unroll
        for (int kc = 0; kc < 4; kc++) {
            uint32_t pa[4];
            pa[0] = packh2(sacc[2 * kc][0],     sacc[2 * kc][1]);
            pa[1] = packh2(sacc[2 * kc][2],     sacc[2 * kc][3]);
            pa[2] = packh2(sacc[2 * kc + 1][0], sacc[2 * kc + 1][1]);
            pa[3] = packh2(sacc[2 * kc + 1][2], sacc[2 * kc + 1][3]);
            int k = kc * 16;
#pragma unroll
            for (int np = 0; np < 8; np++) {
                uint32_t vf[4];
                ldsm_x4t(vf, vs_u + (((k + vrow) * VPH + np * 16 + vcol) << 1));
                mma_h(oacc[np * 2],     pa, vf[0], vf[1]);
                mma_h(oacc[np * 2 + 1], pa, vf[2], vf[3]);
            }
        }
        __syncthreads();
    }

    float inv0 = 1.f / l_i[0];
    float inv1 = 1.f / l_i[1];
#pragma unroll
    for (int nt = 0; nt < 16; nt++) {
        int col = h * DV + nt * 8 + tg * 2;
        *(uint32_t*)&g_attnh[(size_t)r0 * ODIM + col] =
            packh2(oacc[nt][0] * inv0, oacc[nt][1] * inv0);
        *(uint32_t*)&g_attnh[(size_t)r1 * ODIM + col] =
            packh2(oacc[nt][2] * inv1, oacc[nt][3] * inv1);
    }
}

// ---------------- launch ----------------------------------------------------
extern "C" void kernel_launch(void* const* d_in, const int* in_sizes, int n_in,
                              void* d_out, int out_size) {
    const int*   positions = (const int*)d_in[0];
    const float* hidden    = (const float*)d_in[1];
    const float* w_q       = (const float*)d_in[2];
    const float* w_kv_a    = (const float*)d_in[3];
    const float* kv_a_ln_w = (const float*)d_in[4];
    const float* w_kv_b    = (const float*)d_in[5];
    const float* w_o       = (const float*)d_in[6];
    float* out = (float*)d_out;

    __half *p_hidh, *p_wqkvT, *p_wkvbT, *p_woT;
    __half *p_qkvh, *p_kvch, *p_kvbh, *p_attnh;
    cudaGetSymbolAddress((void**)&p_hidh,  g_hidh);
    cudaGetSymbolAddress((void**)&p_wqkvT, g_wqkvT);
    cudaGetSymbolAddress((void**)&p_wkvbT, g_wkvbT);
    cudaGetSymbolAddress((void**)&p_woT,   g_woT);
    cudaGetSymbolAddress((void**)&p_qkvh,  g_qkvh);
    cudaGetSymbolAddress((void**)&p_kvch,  g_kvch);
    cudaGetSymbolAddress((void**)&p_kvbh,  g_kvbh);
    cudaGetSymbolAddress((void**)&p_attnh, g_attnh);

    cudaFuncSetAttribute(gemm_h, cudaFuncAttributeMaxDynamicSharedMemorySize, GEMM_SMEM);
    cudaFuncSetAttribute(attn_h, cudaFuncAttributeMaxDynamicSharedMemorySize, ATT_SMEM);

    // 0. prepass
    convh<<<1024, 256>>>((const float4*)hidden);
    transw_all<<<dim3(KVBDIM / 32, HID / 32, 4), 256>>>(w_q, w_kv_a, w_kv_b, w_o);

    // 1. [q | kv] = hid @ [w_q | w_kv_a]   (fp16 out, N=3648)
    gemm_h<<<dim3((QKVDIM + 127) / 128, T_TOK / 128), 128, GEMM_SMEM>>>(
        p_hidh, p_wqkvT, nullptr, p_qkvh, T_TOK, QKVDIM, HID);
    // 2. rmsnorm + rope
    norm_rope<<<T_TOK, 256>>>(positions, kv_a_ln_w);
    // 3. kvb = kv_c @ w_kv_b (fp16 out)
    gemm_h<<<dim3(KVBDIM / 128, T_TOK / 128), 128, GEMM_SMEM>>>(
        p_kvch, p_wkvbT, nullptr, p_kvbh, T_TOK, KVBDIM, KVD);
    // 4. attention
    attn_h<<<T_TOK / BQ * NH, 256, ATT_SMEM>>>();
    // 5. out = attn @ w_o (fp32 out)
    gemm_h<<<dim3(HID / 128, T_TOK / 128), 128, GEMM_SMEM>>>(
        p_attnh, p_woT, out, nullptr, T_TOK, HID, ODIM);
}

// round 10
// speedup vs baseline: 13.2916x; 1.0226x over previous
#include <cuda_runtime.h>
#include <cuda_fp16.h>
#include <cstdint>
#include <math.h>

// Problem constants
#define T_TOK 2048
#define HID   2048
#define NH    16
#define DN    128
#define DR    64
#define DV    128
#define KVD   512
#define DQK   192
#define QDIM  (NH*DQK)      // 3072
#define KVADIM (KVD + DR)   // 576
#define QKVDIM (QDIM + KVADIM) // 3648
#define KVBDIM (NH*(DN+DV)) // 4096
#define ODIM  (NH*DV)       // 2048
#define ATT_SCALE 0.07216878364870323f

// ---------------- scratch ----------------------------------------------------
__device__ __half g_hidh[(size_t)T_TOK * HID];
__device__ __half g_wqkvT[(size_t)QKVDIM * HID];   // [N][K]
__device__ __half g_wkvbT[(size_t)KVBDIM * KVD];
__device__ __half g_woT [(size_t)HID * ODIM];
__device__ __half g_qkvh[(size_t)T_TOK * QKVDIM];
__device__ __half g_kvch[(size_t)T_TOK * KVD];
__device__ __half g_kpeh[(size_t)T_TOK * DR];
__device__ __half g_kvbh[(size_t)T_TOK * KVBDIM];
__device__ __half g_attnh[(size_t)T_TOK * ODIM];

// ---------------- helpers ----------------------------------------------------
__device__ __forceinline__ uint32_t s2u(const void* p) {
    uint32_t a;
    asm("{ .reg .u64 t; cvta.to.shared.u64 t, %1; cvt.u32.u64 %0, t; }" : "=r"(a) : "l"(p));
    return a;
}
__device__ __forceinline__ void cpa16(uint32_t d, const void* s) {
    asm volatile("cp.async.cg.shared.global [%0], [%1], 16;\n" :: "r"(d), "l"(s));
}
__device__ __forceinline__ void cpa16p(uint32_t d, const void* s, bool pred) {
    int sz = pred ? 16 : 0;
    asm volatile("cp.async.cg.shared.global [%0], [%1], 16, %2;\n" :: "r"(d), "l"(s), "r"(sz));
}
#define CP_COMMIT() asm volatile("cp.async.commit_group;\n")
#define CP_WAIT(N)  asm volatile("cp.async.wait_group %0;\n" :: "n"(N))

__device__ __forceinline__ void ldsm_x4(uint32_t* r, uint32_t a) {
    asm volatile("ldmatrix.sync.aligned.m8n8.x4.shared.b16 {%0,%1,%2,%3}, [%4];"
        : "=r"(r[0]), "=r"(r[1]), "=r"(r[2]), "=r"(r[3]) : "r"(a));
}
__device__ __forceinline__ void ldsm_x4t(uint32_t* r, uint32_t a) {
    asm volatile("ldmatrix.sync.aligned.m8n8.x4.trans.shared.b16 {%0,%1,%2,%3}, [%4];"
        : "=r"(r[0]), "=r"(r[1]), "=r"(r[2]), "=r"(r[3]) : "r"(a));
}
__device__ __forceinline__ void mma_h(float* c, const uint32_t* a, uint32_t b0, uint32_t b1) {
    asm volatile(
        "mma.sync.aligned.m16n8k16.row.col.f32.f16.f16.f32 "
        "{%0,%1,%2,%3}, {%4,%5,%6,%7}, {%8,%9}, {%0,%1,%2,%3};\n"
        : "+f"(c[0]), "+f"(c[1]), "+f"(c[2]), "+f"(c[3])
        : "r"(a[0]), "r"(a[1]), "r"(a[2]), "r"(a[3]), "r"(b0), "r"(b1));
}
__device__ __forceinline__ uint32_t packh2(float x, float y) {
    __half2 h = __floats2half2_rn(x, y);
    return *(uint32_t*)&h;
}

// ---------------- prepass: hidden fp32->fp16 ---------------------------------
__global__ __launch_bounds__(256) void convh(const float4* __restrict__ src) {
    const int n = T_TOK * HID / 4;
    uint2* dst = (uint2*)g_hidh;
    for (int i = blockIdx.x * 256 + threadIdx.x; i < n; i += gridDim.x * 256) {
        float4 v = src[i];
        dst[i] = make_uint2(packh2(v.x, v.y), packh2(v.z, v.w));
    }
}

// ---------------- prepass: batched weight transpose --------------------------
__global__ __launch_bounds__(256) void transw_all(const float* __restrict__ wq,
                                                  const float* __restrict__ wkva,
                                                  const float* __restrict__ wkvb,
                                                  const float* __restrict__ wo) {
    const float* src;
    __half* dst;
    int K, N;
    switch (blockIdx.z) {
        case 0: src = wq;   dst = g_wqkvT;               K = HID; N = QDIM;   break;
        case 1: src = wkva; dst = g_wqkvT + (size_t)QDIM * HID; K = HID; N = KVADIM; break;
        case 2: src = wkvb; dst = g_wkvbT;               K = KVD; N = KVBDIM; break;
        default: src = wo;  dst = g_woT;                 K = ODIM; N = HID;   break;
    }
    int n0 = blockIdx.x * 32, k0 = blockIdx.y * 32;
    if (n0 >= N || k0 >= K) return;
    __shared__ float t[32][33];
    int tx = threadIdx.x & 31;
    int tyy = threadIdx.x >> 5;
#pragma unroll
    for (int j = 0; j < 32; j += 8)
        t[tyy + j][tx] = src[(size_t)(k0 + tyy + j) * N + n0 + tx];
    __syncthreads();
#pragma unroll
    for (int j = 0; j < 32; j += 8)
        dst[(size_t)(n0 + tyy + j) * K + k0 + tx] = __float2half_rn(t[tx][tyy + j]);
}

// ---------------- fp16 GEMM: C[M,N] = A[M,K] @ Bt[N,K]^T ---------------------
// 128x128 CTA tile, 4 warps in 2x2 grid (64x64 warp tiles), BK=32, 3-stage.
#define PH 40
#define STG (128 * PH)
#define GEMM_SMEM (3 * 2 * STG * 2)

__global__ __launch_bounds__(128, 2) void gemm_h(const __half* __restrict__ A,
                                                 const __half* __restrict__ Bt,
                                                 float* __restrict__ Cf,
                                                 __half* __restrict__ Ch,
                                                 int M, int N, int K) {
    extern __shared__ __half smh[];
    __half* As = smh;
    __half* Bs = smh + 3 * STG;
    const uint32_t as_u = s2u(As);
    const uint32_t bs_u = s2u(Bs);

    const int tid = threadIdx.x;
    const int lane = tid & 31;
    const int wid = tid >> 5;
    const int g = lane >> 2;
    const int tg = lane & 3;
    const int wm = wid & 1;
    const int wn = wid >> 1;
    const int crow = blockIdx.y * 128;
    const int ccol = blockIdx.x * 128;

    const int lrow = tid >> 2;
    const int lcol = (tid & 3) << 3;
    const int nk = K >> 5;

    float acc[4][8][4];
#pragma unroll
    for (int mt = 0; mt < 4; mt++)
#pragma unroll
        for (int nt = 0; nt < 8; nt++)
#pragma unroll
            for (int c = 0; c < 4; c++) acc[mt][nt][c] = 0.f;

    auto issue = [&](int kt) {
        int buf = kt % 3;
        int k0 = kt << 5;
        uint32_t au = as_u + (uint32_t)buf * STG * 2;
        uint32_t bu = bs_u + (uint32_t)buf * STG * 2;
#pragma unroll
        for (int i = 0; i < 4; i++) {
            int r = lrow + 32 * i;
            cpa16(au + ((r * PH + lcol) << 1),
                  A + (size_t)(crow + r) * K + k0 + lcol);
            cpa16p(bu + ((r * PH + lcol) << 1),
                   Bt + (size_t)(ccol + r) * K + k0 + lcol, (ccol + r) < N);
        }
    };

    issue(0); CP_COMMIT();
    issue(1); CP_COMMIT();

    const int arow = lane & 15;
    const int acol = (lane >> 4) << 3;
    const int brow = (lane & 7) + ((lane >> 4) << 3);
    const int bcol = ((lane >> 3) & 1) << 3;

    for (int kt = 0; kt < nk; kt++) {
        CP_WAIT(1);
        __syncthreads();
        if (kt + 2 < nk) issue(kt + 2);
        CP_COMMIT();

        int buf = kt % 3;
        uint32_t ab = as_u + (uint32_t)buf * STG * 2;
        uint32_t bb = bs_u + (uint32_t)buf * STG * 2;
#pragma unroll
        for (int ks = 0; ks < 2; ks++) {
            int k = ks << 4;
            uint32_t af[4][4], bf[4][4];
#pragma unroll
            for (int mt = 0; mt < 4; mt++)
                ldsm_x4(af[mt], ab + (((wm * 64 + mt * 16 + arow) * PH + k + acol) << 1));
#pragma unroll
            for (int np = 0; np < 4; np++)
                ldsm_x4(bf[np], bb + (((wn * 64 + np * 16 + brow) * PH + k + bcol) << 1));
#pragma unroll
            for (int mt = 0; mt < 4; mt++)
#pragma unroll
                for (int nt = 0; nt < 8; nt++)
                    mma_h(acc[mt][nt], af[mt],
                          bf[nt >> 1][(nt & 1) * 2], bf[nt >> 1][(nt & 1) * 2 + 1]);
        }
    }

#pragma unroll
    for (int mt = 0; mt < 4; mt++) {
        int row = crow + wm * 64 + mt * 16 + g;
#pragma unroll
        for (int nt = 0; nt < 8; nt++) {
            int col = ccol + wn * 64 + nt * 8 + tg * 2;
            if (col < N) {
                if (Ch) {
                    *(uint32_t*)&Ch[(size_t)row * N + col] =
                        packh2(acc[mt][nt][0], acc[mt][nt][1]);
                    *(uint32_t*)&Ch[(size_t)(row + 8) * N + col] =
                        packh2(acc[mt][nt][2], acc[mt][nt][3]);
                } else {
                    *(float2*)&Cf[(size_t)row * N + col] =
                        make_float2(acc[mt][nt][0], acc[mt][nt][1]);
                    *(float2*)&Cf[(size_t)(row + 8) * N + col] =
                        make_float2(acc[mt][nt][2], acc[mt][nt][3]);
                }
            }
        }
    }
}

// ---------------- RMSNorm + RoPE (fp16 in, fp16 out) -------------------------
__global__ __launch_bounds__(256) void norm_rope(const int* __restrict__ positions,
                                                 const float* __restrict__ lnw) {
    int t   = blockIdx.x;
    int tid = threadIdx.x;
    const __half* kvrow = g_qkvh + (size_t)t * QKVDIM + QDIM;

    float ss = 0.f;
    for (int i = tid; i < KVD; i += 256) {
        float v = __half2float(kvrow[i]);
        ss += v * v;
    }
#pragma unroll
    for (int o = 16; o > 0; o >>= 1) ss += __shfl_xor_sync(0xFFFFFFFFu, ss, o);
    __shared__ float red[8];
    if ((tid & 31) == 0) red[tid >> 5] = ss;
    __syncthreads();
    float tot = 0.f;
#pragma unroll
    for (int w = 0; w < 8; w++) tot += red[w];
    float inv = rsqrtf(tot * (1.f / KVD) + 1e-6f);

    for (int i = tid; i < KVD; i += 256)
        g_kvch[(size_t)t * KVD + i] = __float2half_rn(__half2float(kvrow[i]) * inv * lnw[i]);

    float pos = (float)positions[t];

    for (int i = tid; i < DR / 2; i += 256) {
        float invf = (float)exp(-((double)(2 * i) / (double)DR) * 9.210340371976184);
        float f = pos * invf;
        float c = cosf(f), s = sinf(f);
        __half2 hv = *(__half2*)&kvrow[KVD + 2 * i];
        float x1 = __low2float(hv), x2 = __high2float(hv);
        *(uint32_t*)&g_kpeh[(size_t)t * DR + 2 * i] =
            packh2(x1 * c - x2 * s, x2 * c + x1 * s);
    }

    for (int idx = tid; idx < NH * (DR / 2); idx += 256) {
        int h = idx / (DR / 2);
        int i = idx % (DR / 2);
        float invf = (float)exp(-((double)(2 * i) / (double)DR) * 9.210340371976184);
        float f = pos * invf;
        float c = cosf(f), s = sinf(f);
        uint32_t* qp = (uint32_t*)&g_qkvh[(size_t)t * QKVDIM + h * DQK + DN + 2 * i];
        __half2 hv = *(__half2*)qp;
        float x1 = __low2float(hv), x2 = __high2float(hv);
        *qp = packh2(x1 * c - x2 * s, x2 * c + x1 * s);
    }
}

// ---------------- flash attention, fp16 mma, BQ=64, 128 thr, 2+ CTAs/SM ------
#define BQ 64
#define BKT 64
#define QPH 200
#define VPH 136
#define ATT_SMEM ((BQ * QPH + BKT * QPH + BKT * VPH) * 2)

__global__ __launch_bounds__(128, 2) void attn_h() {
    extern __shared__ __half smh2[];
    __half* Qs = smh2;
    __half* Ks = Qs + BQ * QPH;
    __half* Vs = Ks + BKT * QPH;
    const uint32_t qs_u = s2u(Qs);
    const uint32_t ks_u = s2u(Ks);
    const uint32_t vs_u = s2u(Vs);

    const int bid = blockIdx.x;
    const int qb = 31 - (bid >> 4);   // heavy q-blocks first
    const int h  = bid & 15;
    const int q0 = qb * BQ;
    const int tid = threadIdx.x;
    const int lane = tid & 31;
    const int wid = tid >> 5;         // 0..3
    const int g = lane >> 2;
    const int tg = lane & 3;
    const int m0 = wid * 16;

    // Q tile: 64 rows x 24 chunks = 1536, 128 threads -> 12 iters
#pragma unroll
    for (int i = 0; i < 12; i++) {
        int c = tid + 128 * i;
        int r = c / 24, cc = c % 24;
        cpa16(qs_u + ((r * QPH + cc * 8) << 1),
              g_qkvh + (size_t)(q0 + r) * QKVDIM + h * DQK + cc * 8);
    }
    CP_COMMIT();

    auto issueK = [&](int t0) {
#pragma unroll
        for (int i = 0; i < 12; i++) {
            int c = tid + 128 * i;
            int r = c / 24, cc = c % 24;
            const __half* src = (cc < 16)
                ? g_kvbh + (size_t)(t0 + r) * KVBDIM + h * 256 + cc * 8
                : g_kpeh + (size_t)(t0 + r) * DR + (cc - 16) * 8;
            cpa16(ks_u + ((r * QPH + cc * 8) << 1), src);
        }
    };
    auto issueV = [&](int t0) {
#pragma unroll
        for (int i = 0; i < 8; i++) {
            int c = tid + 128 * i;
            int r = c >> 4, cc = c & 15;
            cpa16(vs_u + ((r * VPH + cc * 8) << 1),
                  g_kvbh + (size_t)(t0 + r) * KVBDIM + h * 256 + DN + cc * 8);
        }
    };

    issueK(0); CP_COMMIT();

    float m_i[2] = {-1e30f, -1e30f};
    float l_i[2] = {0.f, 0.f};
    float oacc[16][4];
#pragma unroll
    for (int nt = 0; nt < 16; nt++)
#pragma unroll
        for (int c = 0; c < 4; c++) oacc[nt][c] = 0.f;

    const int r0 = q0 + m0 + g;
    const int r1 = r0 + 8;
    const int nkb = qb + 1;

    const int arow = lane & 15;
    const int acol = (lane >> 4) << 3;
    const int brow = (lane & 7) + ((lane >> 4) << 3);
    const int bcol = ((lane >> 3) & 1) << 3;
    const int vrow = (lane & 7) + (((lane >> 3) & 1) << 3);
    const int vcol = (lane >> 4) << 3;

    for (int kb = 0; kb < nkb; kb++) {
        int k0 = kb * BKT;
        issueV(k0); CP_COMMIT();
        CP_WAIT(1);
        __syncthreads();

        float sacc[8][4];
#pragma unroll
        for (int nt = 0; nt < 8; nt++)
#pragma unroll
            for (int c = 0; c < 4; c++) sacc[nt][c] = 0.f;
#pragma unroll
        for (int kc = 0; kc < 12; kc++) {
            int k = kc * 16;
            uint32_t af[4], bf[4][4];
            ldsm_x4(af, qs_u + (((m0 + arow) * QPH + k + acol) << 1));
#pragma unroll
            for (int np = 0; np < 4; np++)
                ldsm_x4(bf[np], ks_u + (((np * 16 + brow) * QPH + k + bcol) << 1));
#pragma unroll
            for (int nt = 0; nt < 8; nt++)
                mma_h(sacc[nt], af, bf[nt >> 1][(nt & 1) * 2], bf[nt >> 1][(nt & 1) * 2 + 1]);
        }

        CP_WAIT(0);
        __syncthreads();
        if (kb + 1 < nkb) issueK(k0 + BKT);
        CP_COMMIT();

#pragma unroll
        for (int nt = 0; nt < 8; nt++) {
            int c0i = k0 + nt * 8 + tg * 2;
            sacc[nt][0] = (c0i     <= r0) ? sacc[nt][0] * ATT_SCALE : -1e30f;
            sacc[nt][1] = (c0i + 1 <= r0) ? sacc[nt][1] * ATT_SCALE : -1e30f;
            sacc[nt][2] = (c0i     <= r1) ? sacc[nt][2] * ATT_SCALE : -1e30f;
            sacc[nt][3] = (c0i + 1 <= r1) ? sacc[nt][3] * ATT_SCALE : -1e30f;
        }

        float mx0 = -1e30f, mx1 = -1e30f;
#pragma unroll
        for (int nt = 0; nt < 8; nt++) {
            mx0 = fmaxf(mx0, fmaxf(sacc[nt][0], sacc[nt][1]));
            mx1 = fmaxf(mx1, fmaxf(sacc[nt][2], sacc[nt][3]));
        }
        mx0 = fmaxf(mx0, __shfl_xor_sync(0xFFFFFFFFu, mx0, 1));
        mx0 = fmaxf(mx0, __shfl_xor_sync(0xFFFFFFFFu, mx0, 2));
        mx1 = fmaxf(mx1, __shfl_xor_sync(0xFFFFFFFFu, mx1, 1));
        mx1 = fmaxf(mx1, __shfl_xor_sync(0xFFFFFFFFu, mx1, 2));

        float nm0 = fmaxf(m_i[0], mx0);
        float nm1 = fmaxf(m_i[1], mx1);
        float al0 = __expf(m_i[0] - nm0);
        float al1 = __expf(m_i[1] - nm1);
        m_i[0] = nm0; m_i[1] = nm1;

        float rs0 = 0.f, rs1 = 0.f;
#pragma unroll
        for (int nt = 0; nt < 8; nt++) {
            float p0 = __expf(sacc[nt][0] - nm0);
            float p1 = __expf(sacc[nt][1] - nm0);
            float p2 = __expf(sacc[nt][2] - nm1);
            float p3 = __expf(sacc[nt][3] - nm1);
            sacc[nt][0] = p0; sacc[nt][1] = p1; sacc[nt][2] = p2; sacc[nt][3] = p3;
            rs0 += p0 + p1; rs1 += p2 + p3;
        }
        rs0 += __shfl_xor_sync(0xFFFFFFFFu, rs0, 1);
        rs0 += __shfl_xor_sync(0xFFFFFFFFu, rs0, 2);
        rs1 += __shfl_xor_sync(0xFFFFFFFFu, rs1, 1);
        rs1 += __shfl_xor_sync(0xFFFFFFFFu, rs1, 2);
        l_i[0] = l_i[0] * al0 + rs0;
        l_i[1] = l_i[1] * al1 + rs1;

#pragma unroll
        for (int nt = 0; nt < 16; nt++) {
            oacc[nt][0] *= al0; oacc[nt][1] *= al0;
            oacc[nt][2] *= al1; oacc[nt][3] *= al1;
        }

#pragma unroll
        for (int kc = 0; kc < 4; kc++) {
            uint32_t pa[4];
            pa[0] = packh2(sacc[2 * kc][0],     sacc[2 * kc][1]);
            pa[1] = packh2(sacc[2 * kc][2],     sacc[2 * kc][3]);
            pa[2] = packh2(sacc[2 * kc + 1][0], sacc[2 * kc + 1][1]);
            pa[3] = packh2(sacc[2 * kc + 1][2], sacc[2 * kc + 1][3]);
            int k = kc * 16;
#pragma unroll
            for (int np = 0; np < 8; np++) {
                uint32_t vf[4];
                ldsm_x4t(vf, vs_u + (((k + vrow) * VPH + np * 16 + vcol) << 1));
                mma_h(oacc[np * 2],     pa, vf[0], vf[1]);
                mma_h(oacc[np * 2 + 1], pa, vf[2], vf[3]);
            }
        }
        __syncthreads();
    }

    float inv0 = 1.f / l_i[0];
    float inv1 = 1.f / l_i[1];
#pragma unroll
    for (int nt = 0; nt < 16; nt++) {
        int col = h * DV + nt * 8 + tg * 2;
        *(uint32_t*)&g_attnh[(size_t)r0 * ODIM + col] =
            packh2(oacc[nt][0] * inv0, oacc[nt][1] * inv0);
        *(uint32_t*)&g_attnh[(size_t)r1 * ODIM + col] =
            packh2(oacc[nt][2] * inv1, oacc[nt][3] * inv1);
    }
}

// ---------------- launch ----------------------------------------------------
extern "C" void kernel_launch(void* const* d_in, const int* in_sizes, int n_in,
                              void* d_out, int out_size) {
    const int*   positions = (const int*)d_in[0];
    const float* hidden    = (const float*)d_in[1];
    const float* w_q       = (const float*)d_in[2];
    const float* w_kv_a    = (const float*)d_in[3];
    const float* kv_a_ln_w = (const float*)d_in[4];
    const float* w_kv_b    = (const float*)d_in[5];
    const float* w_o       = (const float*)d_in[6];
    float* out = (float*)d_out;

    __half *p_hidh, *p_wqkvT, *p_wkvbT, *p_woT;
    __half *p_qkvh, *p_kvch, *p_kvbh, *p_attnh;
    cudaGetSymbolAddress((void**)&p_hidh,  g_hidh);
    cudaGetSymbolAddress((void**)&p_wqkvT, g_wqkvT);
    cudaGetSymbolAddress((void**)&p_wkvbT, g_wkvbT);
    cudaGetSymbolAddress((void**)&p_woT,   g_woT);
    cudaGetSymbolAddress((void**)&p_qkvh,  g_qkvh);
    cudaGetSymbolAddress((void**)&p_kvch,  g_kvch);
    cudaGetSymbolAddress((void**)&p_kvbh,  g_kvbh);
    cudaGetSymbolAddress((void**)&p_attnh, g_attnh);

    cudaFuncSetAttribute(gemm_h, cudaFuncAttributeMaxDynamicSharedMemorySize, GEMM_SMEM);
    cudaFuncSetAttribute(attn_h, cudaFuncAttributeMaxDynamicSharedMemorySize, ATT_SMEM);

    // 0. prepass
    convh<<<1024, 256>>>((const float4*)hidden);
    transw_all<<<dim3(KVBDIM / 32, HID / 32, 4), 256>>>(w_q, w_kv_a, w_kv_b, w_o);

    // 1. [q | kv] = hid @ [w_q | w_kv_a]   (fp16 out, N=3648)
    gemm_h<<<dim3((QKVDIM + 127) / 128, T_TOK / 128), 128, GEMM_SMEM>>>(
        p_hidh, p_wqkvT, nullptr, p_qkvh, T_TOK, QKVDIM, HID);
    // 2. rmsnorm + rope
    norm_rope<<<T_TOK, 256>>>(positions, kv_a_ln_w);
    // 3. kvb = kv_c @ w_kv_b (fp16 out)
    gemm_h<<<dim3(KVBDIM / 128, T_TOK / 128), 128, GEMM_SMEM>>>(
        p_kvch, p_wkvbT, nullptr, p_kvbh, T_TOK, KVBDIM, KVD);
    // 4. attention (512 CTAs, heavy-first, 2+ CTAs/SM)
    attn_h<<<T_TOK / BQ * NH, 128, ATT_SMEM>>>();
    // 5. out = attn @ w_o (fp32 out)
    gemm_h<<<dim3(HID / 128, T_TOK / 128), 128, GEMM_SMEM>>>(
        p_attnh, p_woT, out, nullptr, T_TOK, HID, ODIM);
}